// round 8
// baseline (speedup 1.0000x reference)
#include <cuda_runtime.h>

// ---------------------------------------------------------------------------
// Problem constants
// ---------------------------------------------------------------------------
#define DIMX   1024
#define NH     16
#define HD     64
#define BATCH  4
#define SEQ    2048
#define ROWS   (BATCH * SEQ)        // 8192
#define QKVD   (3 * DIMX)           // 3072

// Scratch (allocations are forbidden; __device__ globals are the sanctioned path)
__device__ float g_qkv[(size_t)ROWS * QKVD];   // 96 MB
__device__ float g_att[(size_t)ROWS * DIMX];   // 32 MB

typedef unsigned long long u64;

// ---------------------------------------------------------------------------
// Packed fp32x2 helpers (Blackwell 2xFP32 datapath, SASS FFMA2)
// ---------------------------------------------------------------------------
__device__ __forceinline__ u64 pack2(float lo, float hi) {
    u64 r;
    asm("mov.b64 %0, {%1, %2};" : "=l"(r) : "f"(lo), "f"(hi));
    return r;
}
__device__ __forceinline__ u64 ffma2(u64 a, u64 b, u64 c) {
    u64 d;
    asm("fma.rn.f32x2 %0, %1, %2, %3;" : "=l"(d) : "l"(a), "l"(b), "l"(c));
    return d;
}

// ---------------------------------------------------------------------------
// NT SGEMM:  C[M,N] = A[M,K] * B[N,K]^T   (both row-major, K contiguous)
// 128x128 tile, BK=16, 256 threads, 8x8 per thread, packed f32x2 accumulators.
// A tile is stored DUPLICATED ((v,v) u64) in smem so the inner loop needs no
// packing MOVs: 6 x LDS.128 + 32 x FFMA2 per k-step.
// ---------------------------------------------------------------------------
#define AP 130   // As2 pitch (u64)
#define BP 132   // Bs  pitch (float)

__global__ __launch_bounds__(256, 2)
void gemm_nt(const float* __restrict__ A,
             const float* __restrict__ B,
             float* __restrict__ C,
             int M, int N, int K) {
    __shared__ u64   As2[16 * AP];
    __shared__ float Bs [16 * BP];

    const int tid = threadIdx.x;
    const int tx  = tid & 15;
    const int ty  = tid >> 4;
    const int bm  = blockIdx.y * 128;
    const int bn  = blockIdx.x * 128;

    const int lrow = tid >> 2;            // 0..63
    const int lcol = (tid & 3) << 2;      // 0,4,8,12

    const float* Ab = A + (size_t)(bm + lrow) * K + lcol;
    const float* Bb = B + (size_t)(bn + lrow) * K + lcol;

    u64 acc[8][4];
#pragma unroll
    for (int i = 0; i < 8; i++)
#pragma unroll
        for (int j = 0; j < 4; j++) acc[i][j] = 0ull;

    // register-staged double buffer
    float4 ra0 = *(const float4*)(Ab);
    float4 ra1 = *(const float4*)(Ab + (size_t)64 * K);
    float4 rb0 = *(const float4*)(Bb);
    float4 rb1 = *(const float4*)(Bb + (size_t)64 * K);

    const int nt = K >> 4;
    for (int t = 0; t < nt; t++) {
        // commit staged tile to smem (A duplicated, B transposed)
        As2[(lcol + 0) * AP + lrow]      = pack2(ra0.x, ra0.x);
        As2[(lcol + 1) * AP + lrow]      = pack2(ra0.y, ra0.y);
        As2[(lcol + 2) * AP + lrow]      = pack2(ra0.z, ra0.z);
        As2[(lcol + 3) * AP + lrow]      = pack2(ra0.w, ra0.w);
        As2[(lcol + 0) * AP + lrow + 64] = pack2(ra1.x, ra1.x);
        As2[(lcol + 1) * AP + lrow + 64] = pack2(ra1.y, ra1.y);
        As2[(lcol + 2) * AP + lrow + 64] = pack2(ra1.z, ra1.z);
        As2[(lcol + 3) * AP + lrow + 64] = pack2(ra1.w, ra1.w);

        Bs[(lcol + 0) * BP + lrow]      = rb0.x;
        Bs[(lcol + 1) * BP + lrow]      = rb0.y;
        Bs[(lcol + 2) * BP + lrow]      = rb0.z;
        Bs[(lcol + 3) * BP + lrow]      = rb0.w;
        Bs[(lcol + 0) * BP + lrow + 64] = rb1.x;
        Bs[(lcol + 1) * BP + lrow + 64] = rb1.y;
        Bs[(lcol + 2) * BP + lrow + 64] = rb1.z;
        Bs[(lcol + 3) * BP + lrow + 64] = rb1.w;
        __syncthreads();

        if (t + 1 < nt) {   // prefetch next tile into registers (overlaps compute)
            const float* An = Ab + (size_t)(t + 1) * 16;
            const float* Bn = Bb + (size_t)(t + 1) * 16;
            ra0 = *(const float4*)(An);
            ra1 = *(const float4*)(An + (size_t)64 * K);
            rb0 = *(const float4*)(Bn);
            rb1 = *(const float4*)(Bn + (size_t)64 * K);
        }

#pragma unroll
        for (int k = 0; k < 16; k++) {
            u64 a2[8], b2[4];
            ulonglong2 q0 = *(const ulonglong2*)(&As2[k * AP + ty * 8 + 0]);
            ulonglong2 q1 = *(const ulonglong2*)(&As2[k * AP + ty * 8 + 2]);
            ulonglong2 q2 = *(const ulonglong2*)(&As2[k * AP + ty * 8 + 4]);
            ulonglong2 q3 = *(const ulonglong2*)(&As2[k * AP + ty * 8 + 6]);
            a2[0] = q0.x; a2[1] = q0.y; a2[2] = q1.x; a2[3] = q1.y;
            a2[4] = q2.x; a2[5] = q2.y; a2[6] = q3.x; a2[7] = q3.y;
            ulonglong2 w0 = *(const ulonglong2*)(&Bs[k * BP + tx * 8 + 0]);
            ulonglong2 w1 = *(const ulonglong2*)(&Bs[k * BP + tx * 8 + 4]);
            b2[0] = w0.x; b2[1] = w0.y; b2[2] = w1.x; b2[3] = w1.y;
#pragma unroll
            for (int i = 0; i < 8; i++)
#pragma unroll
                for (int j = 0; j < 4; j++)
                    acc[i][j] = ffma2(a2[i], b2[j], acc[i][j]);
        }
        __syncthreads();
    }

#pragma unroll
    for (int i = 0; i < 8; i++) {
        float* Cp = C + (size_t)(bm + ty * 8 + i) * N + bn + tx * 8;
        ulonglong2 s0; s0.x = acc[i][0]; s0.y = acc[i][1];
        ulonglong2 s1; s1.x = acc[i][2]; s1.y = acc[i][3];
        *(ulonglong2*)(Cp)     = s0;
        *(ulonglong2*)(Cp + 4) = s1;
    }
}

// ---------------------------------------------------------------------------
// Causal flash attention, fp32.
// Block = 64 query rows for one (b,h). 256 threads, thread = 4x4 micro-tile.
// Q/K stored d-major (transposed) in smem -> conflict-free float4 loads in the
// S outer-product loop; P stored key-major for the PV contraction.
// smem = 4 * 64 * 68 * 4B = 69632 B (dynamic), 2 CTAs/SM.
// ---------------------------------------------------------------------------
#define APITCH 68
#define SMEM_ATTN (4 * 64 * APITCH * 4)

__global__ __launch_bounds__(256, 2)
void attn_kernel() {
    extern __shared__ float smf[];
    float* Qs = smf;                    // [d][row]
    float* Ks = smf + 64 * APITCH;      // [d][col]
    float* Vs = smf + 2 * 64 * APITCH;  // [kk][d]
    float* Ps = smf + 3 * 64 * APITCH;  // [kk][row]

    const int tid = threadIdx.x;
    const int tx  = tid & 15;
    const int ty  = tid >> 4;
    const int qb  = blockIdx.x;
    const int h   = blockIdx.y;
    const int b   = blockIdx.z;
    const int r0  = ty << 2;
    const int c0  = tx << 2;

    const int rr = tid >> 2;            // 0..63
    const int dg = (tid & 3) << 2;      // 0,4,8,12

    // ---- load Q (scaled by Hd^-0.5 = 0.125) transposed ----
    {
        const float* gq = g_qkv + (size_t)(b * SEQ + qb * 64) * QKVD + h * HD;
#pragma unroll
        for (int p = 0; p < 4; p++) {
            int d0 = dg + p * 16;
            float4 v = *(const float4*)(gq + (size_t)rr * QKVD + d0);
            Qs[(d0 + 0) * APITCH + rr] = v.x * 0.125f;
            Qs[(d0 + 1) * APITCH + rr] = v.y * 0.125f;
            Qs[(d0 + 2) * APITCH + rr] = v.z * 0.125f;
            Qs[(d0 + 3) * APITCH + rr] = v.w * 0.125f;
        }
    }

    float m_i[4], l_i[4], o[4][4];
#pragma unroll
    for (int i = 0; i < 4; i++) {
        m_i[i] = -1e30f; l_i[i] = 0.f;
#pragma unroll
        for (int j = 0; j < 4; j++) o[i][j] = 0.f;
    }

    for (int kb = 0; kb <= qb; kb++) {
        __syncthreads();   // previous iteration done reading Ks/Vs/Ps
        {
            const float* gk = g_qkv + (size_t)(b * SEQ + kb * 64) * QKVD + DIMX + h * HD;
            const float* gv = gk + DIMX;
#pragma unroll
            for (int p = 0; p < 4; p++) {
                int d0 = dg + p * 16;
                float4 kv = *(const float4*)(gk + (size_t)rr * QKVD + d0);
                Ks[(d0 + 0) * APITCH + rr] = kv.x;
                Ks[(d0 + 1) * APITCH + rr] = kv.y;
                Ks[(d0 + 2) * APITCH + rr] = kv.z;
                Ks[(d0 + 3) * APITCH + rr] = kv.w;
                float4 vv = *(const float4*)(gv + (size_t)rr * QKVD + d0);
                *(float4*)(Vs + rr * APITCH + d0) = vv;
            }
        }
        __syncthreads();

        // ---- S = Q K^T (4x4 per thread) ----
        float s[4][4];
#pragma unroll
        for (int i = 0; i < 4; i++)
#pragma unroll
            for (int j = 0; j < 4; j++) s[i][j] = 0.f;

#pragma unroll 8
        for (int d = 0; d < 64; d++) {
            float4 a  = *(const float4*)(Qs + d * APITCH + r0);
            float4 bb = *(const float4*)(Ks + d * APITCH + c0);
            s[0][0] += a.x * bb.x; s[0][1] += a.x * bb.y; s[0][2] += a.x * bb.z; s[0][3] += a.x * bb.w;
            s[1][0] += a.y * bb.x; s[1][1] += a.y * bb.y; s[1][2] += a.y * bb.z; s[1][3] += a.y * bb.w;
            s[2][0] += a.z * bb.x; s[2][1] += a.z * bb.y; s[2][2] += a.z * bb.z; s[2][3] += a.z * bb.w;
            s[3][0] += a.w * bb.x; s[3][1] += a.w * bb.y; s[3][2] += a.w * bb.z; s[3][3] += a.w * bb.w;
        }

        if (kb == qb) {   // causal mask on the diagonal block
#pragma unroll
            for (int i = 0; i < 4; i++)
#pragma unroll
                for (int j = 0; j < 4; j++)
                    if (c0 + j > r0 + i) s[i][j] = -1e30f;
        }

        // ---- online softmax (row groups span 16 lanes) ----
#pragma unroll
        for (int i = 0; i < 4; i++) {
            float rm = fmaxf(fmaxf(s[i][0], s[i][1]), fmaxf(s[i][2], s[i][3]));
            rm = fmaxf(rm, __shfl_xor_sync(0xffffffffu, rm, 8));
            rm = fmaxf(rm, __shfl_xor_sync(0xffffffffu, rm, 4));
            rm = fmaxf(rm, __shfl_xor_sync(0xffffffffu, rm, 2));
            rm = fmaxf(rm, __shfl_xor_sync(0xffffffffu, rm, 1));
            float mnew  = fmaxf(m_i[i], rm);
            float alpha = __expf(m_i[i] - mnew);
            m_i[i] = mnew;
            float rs = 0.f;
#pragma unroll
            for (int j = 0; j < 4; j++) {
                float pv = __expf(s[i][j] - mnew);
                s[i][j] = pv;
                rs += pv;
            }
            rs += __shfl_xor_sync(0xffffffffu, rs, 8);
            rs += __shfl_xor_sync(0xffffffffu, rs, 4);
            rs += __shfl_xor_sync(0xffffffffu, rs, 2);
            rs += __shfl_xor_sync(0xffffffffu, rs, 1);
            l_i[i] = l_i[i] * alpha + rs;
#pragma unroll
            for (int j = 0; j < 4; j++) o[i][j] *= alpha;
        }

        // ---- write P transposed: Ps[key][row] ----
#pragma unroll
        for (int j = 0; j < 4; j++) {
            float4 pv = make_float4(s[0][j], s[1][j], s[2][j], s[3][j]);
            *(float4*)(Ps + (c0 + j) * APITCH + r0) = pv;
        }
        __syncthreads();

        // ---- O += P V ----
#pragma unroll 8
        for (int kk = 0; kk < 64; kk++) {
            float4 a  = *(const float4*)(Ps + kk * APITCH + r0);
            float4 vb = *(const float4*)(Vs + kk * APITCH + c0);
            o[0][0] += a.x * vb.x; o[0][1] += a.x * vb.y; o[0][2] += a.x * vb.z; o[0][3] += a.x * vb.w;
            o[1][0] += a.y * vb.x; o[1][1] += a.y * vb.y; o[1][2] += a.y * vb.z; o[1][3] += a.y * vb.w;
            o[2][0] += a.z * vb.x; o[2][1] += a.z * vb.y; o[2][2] += a.z * vb.z; o[2][3] += a.z * vb.w;
            o[3][0] += a.w * vb.x; o[3][1] += a.w * vb.y; o[3][2] += a.w * vb.z; o[3][3] += a.w * vb.w;
        }
    }

    // ---- finalize and write [B, L, (h d)] ----
    float* ga = g_att + (size_t)(b * SEQ + qb * 64 + r0) * DIMX + h * HD + c0;
#pragma unroll
    for (int i = 0; i < 4; i++) {
        float inv = 1.0f / l_i[i];
        float4 ov = make_float4(o[i][0] * inv, o[i][1] * inv, o[i][2] * inv, o[i][3] * inv);
        *(float4*)(ga + (size_t)i * DIMX) = ov;
    }
}

// ---------------------------------------------------------------------------
// launch
// ---------------------------------------------------------------------------
extern "C" void kernel_launch(void* const* d_in, const int* in_sizes, int n_in,
                              void* d_out, int out_size) {
    const float* x     = (const float*)d_in[0];   // [4,2048,1024]
    const float* Wqkv  = (const float*)d_in[1];   // [3072,1024]
    const float* Wout  = (const float*)d_in[2];   // [1024,1024]
    float*       out   = (float*)d_out;           // [4,2048,1024]

    float* qkv = nullptr;
    float* att = nullptr;
    cudaGetSymbolAddress((void**)&qkv, g_qkv);
    cudaGetSymbolAddress((void**)&att, g_att);

    cudaFuncSetAttribute(attn_kernel, cudaFuncAttributeMaxDynamicSharedMemorySize,
                         SMEM_ATTN);

    // 1) qkv = x @ Wqkv^T    [8192,3072]
    dim3 g1(QKVD / 128, ROWS / 128);
    gemm_nt<<<g1, 256>>>(x, Wqkv, qkv, ROWS, QKVD, DIMX);

    // 2) causal attention -> g_att [8192,1024]
    dim3 g2(SEQ / 64, NH, BATCH);
    attn_kernel<<<g2, 256, SMEM_ATTN>>>();

    // 3) out = att @ Wout^T  [8192,1024]
    dim3 g3(DIMX / 128, ROWS / 128);
    gemm_nt<<<g3, 256>>>(att, Wout, out, ROWS, DIMX, DIMX);
}

// round 11
// speedup vs baseline: 1.6414x; 1.6414x over previous
#include <cuda_runtime.h>
#include <cstdint>

// ---------------------------------------------------------------------------
// Problem constants
// ---------------------------------------------------------------------------
#define DIMX   1024
#define NH     16
#define HD     64
#define BATCH  4
#define SEQ    2048
#define ROWS   (BATCH * SEQ)        // 8192
#define QKVD   (3 * DIMX)           // 3072
#define KH     (DIMX / 2)           // 512 u32 (bf16x2 pairs) per row

// ---------------------------------------------------------------------------
// Scratch (__device__ globals; allocation is forbidden)
// ---------------------------------------------------------------------------
__device__ float    g_qkv[(size_t)ROWS * QKVD];   // 96 MB (attention input, fp32)
__device__ float    g_att[(size_t)ROWS * DIMX];   // 32 MB (attention output, fp32)
__device__ uint32_t g_xh [(size_t)ROWS * KH];     // x   hi (bf16x2)
__device__ uint32_t g_xl [(size_t)ROWS * KH];     // x   lo
__device__ uint32_t g_wqh[(size_t)QKVD * KH];     // Wqkv hi
__device__ uint32_t g_wql[(size_t)QKVD * KH];     // Wqkv lo
__device__ uint32_t g_woh[(size_t)DIMX * KH];     // Wout hi
__device__ uint32_t g_wol[(size_t)DIMX * KH];     // Wout lo
__device__ uint32_t g_ah [(size_t)ROWS * KH];     // att hi
__device__ uint32_t g_al [(size_t)ROWS * KH];     // att lo

// ---------------------------------------------------------------------------
// fp32 -> (bf16 hi, bf16 lo) split, packed as bf16x2 pairs (low k in low 16b)
// ---------------------------------------------------------------------------
__global__ __launch_bounds__(256)
void cvt_split(const float* __restrict__ src,
               uint32_t* __restrict__ hi, uint32_t* __restrict__ lo, int n2) {
    int i = blockIdx.x * blockDim.x + threadIdx.x;
    if (i >= n2) return;
    float2 v = ((const float2*)src)[i];
    uint32_t h;
    asm("cvt.rn.bf16x2.f32 %0, %1, %2;" : "=r"(h) : "f"(v.y), "f"(v.x));
    float hx = __uint_as_float(h << 16);
    float hy = __uint_as_float(h & 0xFFFF0000u);
    float lx = v.x - hx;
    float ly = v.y - hy;
    uint32_t l;
    asm("cvt.rn.bf16x2.f32 %0, %1, %2;" : "=r"(l) : "f"(ly), "f"(lx));
    hi[i] = h;
    lo[i] = l;
}

// ---------------------------------------------------------------------------
// mma.sync m16n8k16 bf16 (row.col), fp32 accumulate
// ---------------------------------------------------------------------------
__device__ __forceinline__ void mma_bf16(float* d, const uint32_t* a, const uint32_t* b) {
    asm volatile(
        "mma.sync.aligned.m16n8k16.row.col.f32.bf16.bf16.f32 "
        "{%0,%1,%2,%3}, {%4,%5,%6,%7}, {%8,%9}, {%0,%1,%2,%3};"
        : "+f"(d[0]), "+f"(d[1]), "+f"(d[2]), "+f"(d[3])
        : "r"(a[0]), "r"(a[1]), "r"(a[2]), "r"(a[3]), "r"(b[0]), "r"(b[1]));
}

// ---------------------------------------------------------------------------
// 3-term bf16 NT GEMM:  C[M,N] = A[M,K] * B[N,K]^T   (fp32 out)
// A,B given as split bf16x2 arrays: [rows][K/2] u32 (hi and lo).
// CTA 128x128, 256 threads (8 warps = 2x4), warp tile 64x32 (m16n8k16 4x4).
// Smem: [row][kp] u32 with XOR swizzle col' = kp ^ (row & 7); double buffered.
// ---------------------------------------------------------------------------
#define P_AH 0
#define P_AL 1024
#define P_BH 2048
#define P_BL 3072
#define BUFSZ 4096

__device__ __forceinline__ void stage_store(uint32_t* dst, uint32_t i0, uint32_t i1,
                                            uint4 v, int swp) {
    uint2 p0, p1;
    if (swp) { p0 = make_uint2(v.y, v.x); p1 = make_uint2(v.w, v.z); }
    else     { p0 = make_uint2(v.x, v.y); p1 = make_uint2(v.z, v.w); }
    *(uint2*)(dst + i0) = p0;
    *(uint2*)(dst + i1) = p1;
}

__global__ __launch_bounds__(256, 2)
void gemm_bf3(const uint32_t* __restrict__ Ah, const uint32_t* __restrict__ Al,
              const uint32_t* __restrict__ Bh, const uint32_t* __restrict__ Bl,
              float* __restrict__ C, int M, int N, int K) {
    __shared__ uint32_t smbuf[2 * BUFSZ];   // 32 KB

    const int tid   = threadIdx.x;
    const int lane  = tid & 31;
    const int wid   = tid >> 5;
    const int warpm = wid >> 2;       // 0..1
    const int warpn = wid & 3;        // 0..3
    const int g     = lane >> 2;      // 0..7
    const int tg    = lane & 3;       // 0..3
    const int bm    = blockIdx.y << 7;
    const int bn    = blockIdx.x << 7;
    const int KP    = K >> 1;

    // --- staging assignment: thread = (row, half); ldg.128 = 4 u32 = 2 pairs
    const int srow  = tid >> 1;       // 0..127
    const int shalf = tid & 1;        // 0..1
    const int s     = srow & 7;
    const int swp   = s & 1;
    const uint32_t i0 = (uint32_t)srow * 8 + ((4 * shalf)     ^ (s & 6));
    const uint32_t i1 = (uint32_t)srow * 8 + ((4 * shalf + 2) ^ (s & 6));

    const uint32_t* pAh = Ah + (size_t)(bm + srow) * KP + shalf * 4;
    const uint32_t* pAl = Al + (size_t)(bm + srow) * KP + shalf * 4;
    const uint32_t* pBh = Bh + (size_t)(bn + srow) * KP + shalf * 4;
    const uint32_t* pBl = Bl + (size_t)(bn + srow) * KP + shalf * 4;

    float acc[4][4][4];
#pragma unroll
    for (int i = 0; i < 4; i++)
#pragma unroll
        for (int j = 0; j < 4; j++)
#pragma unroll
            for (int q = 0; q < 4; q++) acc[i][j][q] = 0.f;

    const int nt = K >> 4;            // chunks of 16 k-values (8 u32)

    // prologue: chunk 0 -> buf 0
    uint4 vah = *(const uint4*)(pAh);
    uint4 val = *(const uint4*)(pAl);
    uint4 vbh = *(const uint4*)(pBh);
    uint4 vbl = *(const uint4*)(pBl);
    stage_store(smbuf + P_AH, i0, i1, vah, swp);
    stage_store(smbuf + P_AL, i0, i1, val, swp);
    stage_store(smbuf + P_BH, i0, i1, vbh, swp);
    stage_store(smbuf + P_BL, i0, i1, vbl, swp);
    __syncthreads();

    const int c0 = tg ^ g;
    const int c1 = (tg + 4) ^ g;

    for (int t = 0; t < nt; t++) {
        const uint32_t* S = smbuf + (t & 1) * BUFSZ;

        if (t + 1 < nt) {
            vah = *(const uint4*)(pAh + (t + 1) * 8);
            val = *(const uint4*)(pAl + (t + 1) * 8);
            vbh = *(const uint4*)(pBh + (t + 1) * 8);
            vbl = *(const uint4*)(pBl + (t + 1) * 8);
        }

        uint32_t a[4][4], b[4][2];

        // ---- term 1: Ah * Bh ----
#pragma unroll
        for (int i = 0; i < 4; i++) {
            int r = warpm * 64 + i * 16 + g;
            a[i][0] = S[P_AH + r * 8 + c0];
            a[i][1] = S[P_AH + (r + 8) * 8 + c0];
            a[i][2] = S[P_AH + r * 8 + c1];
            a[i][3] = S[P_AH + (r + 8) * 8 + c1];
        }
#pragma unroll
        for (int j = 0; j < 4; j++) {
            int n = warpn * 32 + j * 8 + g;
            b[j][0] = S[P_BH + n * 8 + c0];
            b[j][1] = S[P_BH + n * 8 + c1];
        }
#pragma unroll
        for (int i = 0; i < 4; i++)
#pragma unroll
            for (int j = 0; j < 4; j++) mma_bf16(acc[i][j], a[i], b[j]);

        // ---- term 2: Al * Bh ----
#pragma unroll
        for (int i = 0; i < 4; i++) {
            int r = warpm * 64 + i * 16 + g;
            a[i][0] = S[P_AL + r * 8 + c0];
            a[i][1] = S[P_AL + (r + 8) * 8 + c0];
            a[i][2] = S[P_AL + r * 8 + c1];
            a[i][3] = S[P_AL + (r + 8) * 8 + c1];
        }
#pragma unroll
        for (int i = 0; i < 4; i++)
#pragma unroll
            for (int j = 0; j < 4; j++) mma_bf16(acc[i][j], a[i], b[j]);

        // ---- term 3: Ah * Bl ----
#pragma unroll
        for (int i = 0; i < 4; i++) {
            int r = warpm * 64 + i * 16 + g;
            a[i][0] = S[P_AH + r * 8 + c0];
            a[i][1] = S[P_AH + (r + 8) * 8 + c0];
            a[i][2] = S[P_AH + r * 8 + c1];
            a[i][3] = S[P_AH + (r + 8) * 8 + c1];
        }
#pragma unroll
        for (int j = 0; j < 4; j++) {
            int n = warpn * 32 + j * 8 + g;
            b[j][0] = S[P_BL + n * 8 + c0];
            b[j][1] = S[P_BL + n * 8 + c1];
        }
#pragma unroll
        for (int i = 0; i < 4; i++)
#pragma unroll
            for (int j = 0; j < 4; j++) mma_bf16(acc[i][j], a[i], b[j]);

        if (t + 1 < nt) {
            uint32_t* D = smbuf + ((t + 1) & 1) * BUFSZ;
            stage_store(D + P_AH, i0, i1, vah, swp);
            stage_store(D + P_AL, i0, i1, val, swp);
            stage_store(D + P_BH, i0, i1, vbh, swp);
            stage_store(D + P_BL, i0, i1, vbl, swp);
        }
        __syncthreads();
    }

    // ---- epilogue ----
#pragma unroll
    for (int i = 0; i < 4; i++) {
        int row = bm + warpm * 64 + i * 16 + g;
#pragma unroll
        for (int j = 0; j < 4; j++) {
            int col = bn + warpn * 32 + j * 8 + 2 * tg;
            float2 v0 = make_float2(acc[i][j][0], acc[i][j][1]);
            float2 v1 = make_float2(acc[i][j][2], acc[i][j][3]);
            *(float2*)&C[(size_t)row * N + col]       = v0;
            *(float2*)&C[(size_t)(row + 8) * N + col] = v1;
        }
    }
}

// ---------------------------------------------------------------------------
// Causal flash attention, fp32 (unchanged — proven at ~0.9ms, rel_err 1e-6)
// ---------------------------------------------------------------------------
#define APITCH 68
#define SMEM_ATTN (4 * 64 * APITCH * 4)

__global__ __launch_bounds__(256, 2)
void attn_kernel() {
    extern __shared__ float smf[];
    float* Qs = smf;                    // [d][row]
    float* Ks = smf + 64 * APITCH;      // [d][col]
    float* Vs = smf + 2 * 64 * APITCH;  // [kk][d]
    float* Ps = smf + 3 * 64 * APITCH;  // [kk][row]

    const int tid = threadIdx.x;
    const int tx  = tid & 15;
    const int ty  = tid >> 4;
    const int qb  = blockIdx.x;
    const int h   = blockIdx.y;
    const int b   = blockIdx.z;
    const int r0  = ty << 2;
    const int c0  = tx << 2;

    const int rr = tid >> 2;            // 0..63
    const int dg = (tid & 3) << 2;      // 0,4,8,12

    {
        const float* gq = g_qkv + (size_t)(b * SEQ + qb * 64) * QKVD + h * HD;
#pragma unroll
        for (int p = 0; p < 4; p++) {
            int d0 = dg + p * 16;
            float4 v = *(const float4*)(gq + (size_t)rr * QKVD + d0);
            Qs[(d0 + 0) * APITCH + rr] = v.x * 0.125f;
            Qs[(d0 + 1) * APITCH + rr] = v.y * 0.125f;
            Qs[(d0 + 2) * APITCH + rr] = v.z * 0.125f;
            Qs[(d0 + 3) * APITCH + rr] = v.w * 0.125f;
        }
    }

    float m_i[4], l_i[4], o[4][4];
#pragma unroll
    for (int i = 0; i < 4; i++) {
        m_i[i] = -1e30f; l_i[i] = 0.f;
#pragma unroll
        for (int j = 0; j < 4; j++) o[i][j] = 0.f;
    }

    for (int kb = 0; kb <= qb; kb++) {
        __syncthreads();
        {
            const float* gk = g_qkv + (size_t)(b * SEQ + kb * 64) * QKVD + DIMX + h * HD;
            const float* gv = gk + DIMX;
#pragma unroll
            for (int p = 0; p < 4; p++) {
                int d0 = dg + p * 16;
                float4 kv = *(const float4*)(gk + (size_t)rr * QKVD + d0);
                Ks[(d0 + 0) * APITCH + rr] = kv.x;
                Ks[(d0 + 1) * APITCH + rr] = kv.y;
                Ks[(d0 + 2) * APITCH + rr] = kv.z;
                Ks[(d0 + 3) * APITCH + rr] = kv.w;
                float4 vv = *(const float4*)(gv + (size_t)rr * QKVD + d0);
                *(float4*)(Vs + rr * APITCH + d0) = vv;
            }
        }
        __syncthreads();

        float s[4][4];
#pragma unroll
        for (int i = 0; i < 4; i++)
#pragma unroll
            for (int j = 0; j < 4; j++) s[i][j] = 0.f;

#pragma unroll 8
        for (int d = 0; d < 64; d++) {
            float4 a  = *(const float4*)(Qs + d * APITCH + r0);
            float4 bb = *(const float4*)(Ks + d * APITCH + c0);
            s[0][0] += a.x * bb.x; s[0][1] += a.x * bb.y; s[0][2] += a.x * bb.z; s[0][3] += a.x * bb.w;
            s[1][0] += a.y * bb.x; s[1][1] += a.y * bb.y; s[1][2] += a.y * bb.z; s[1][3] += a.y * bb.w;
            s[2][0] += a.z * bb.x; s[2][1] += a.z * bb.y; s[2][2] += a.z * bb.z; s[2][3] += a.z * bb.w;
            s[3][0] += a.w * bb.x; s[3][1] += a.w * bb.y; s[3][2] += a.w * bb.z; s[3][3] += a.w * bb.w;
        }

        if (kb == qb) {
#pragma unroll
            for (int i = 0; i < 4; i++)
#pragma unroll
                for (int j = 0; j < 4; j++)
                    if (c0 + j > r0 + i) s[i][j] = -1e30f;
        }

#pragma unroll
        for (int i = 0; i < 4; i++) {
            float rm = fmaxf(fmaxf(s[i][0], s[i][1]), fmaxf(s[i][2], s[i][3]));
            rm = fmaxf(rm, __shfl_xor_sync(0xffffffffu, rm, 8));
            rm = fmaxf(rm, __shfl_xor_sync(0xffffffffu, rm, 4));
            rm = fmaxf(rm, __shfl_xor_sync(0xffffffffu, rm, 2));
            rm = fmaxf(rm, __shfl_xor_sync(0xffffffffu, rm, 1));
            float mnew  = fmaxf(m_i[i], rm);
            float alpha = __expf(m_i[i] - mnew);
            m_i[i] = mnew;
            float rs = 0.f;
#pragma unroll
            for (int j = 0; j < 4; j++) {
                float pv = __expf(s[i][j] - mnew);
                s[i][j] = pv;
                rs += pv;
            }
            rs += __shfl_xor_sync(0xffffffffu, rs, 8);
            rs += __shfl_xor_sync(0xffffffffu, rs, 4);
            rs += __shfl_xor_sync(0xffffffffu, rs, 2);
            rs += __shfl_xor_sync(0xffffffffu, rs, 1);
            l_i[i] = l_i[i] * alpha + rs;
#pragma unroll
            for (int j = 0; j < 4; j++) o[i][j] *= alpha;
        }

#pragma unroll
        for (int j = 0; j < 4; j++) {
            float4 pv = make_float4(s[0][j], s[1][j], s[2][j], s[3][j]);
            *(float4*)(Ps + (c0 + j) * APITCH + r0) = pv;
        }
        __syncthreads();

#pragma unroll 8
        for (int kk = 0; kk < 64; kk++) {
            float4 a  = *(const float4*)(Ps + kk * APITCH + r0);
            float4 vb = *(const float4*)(Vs + kk * APITCH + c0);
            o[0][0] += a.x * vb.x; o[0][1] += a.x * vb.y; o[0][2] += a.x * vb.z; o[0][3] += a.x * vb.w;
            o[1][0] += a.y * vb.x; o[1][1] += a.y * vb.y; o[1][2] += a.y * vb.z; o[1][3] += a.y * vb.w;
            o[2][0] += a.z * vb.x; o[2][1] += a.z * vb.y; o[2][2] += a.z * vb.z; o[2][3] += a.z * vb.w;
            o[3][0] += a.w * vb.x; o[3][1] += a.w * vb.y; o[3][2] += a.w * vb.z; o[3][3] += a.w * vb.w;
        }
    }

    float* ga = g_att + (size_t)(b * SEQ + qb * 64 + r0) * DIMX + h * HD + c0;
#pragma unroll
    for (int i = 0; i < 4; i++) {
        float inv = 1.0f / l_i[i];
        float4 ov = make_float4(o[i][0] * inv, o[i][1] * inv, o[i][2] * inv, o[i][3] * inv);
        *(float4*)(ga + (size_t)i * DIMX) = ov;
    }
}

// ---------------------------------------------------------------------------
// launch
// ---------------------------------------------------------------------------
extern "C" void kernel_launch(void* const* d_in, const int* in_sizes, int n_in,
                              void* d_out, int out_size) {
    const float* x    = (const float*)d_in[0];   // [4,2048,1024]
    const float* Wqkv = (const float*)d_in[1];   // [3072,1024]
    const float* Wout = (const float*)d_in[2];   // [1024,1024]
    float*       out  = (float*)d_out;           // [4,2048,1024]

    float *qkv = nullptr, *att = nullptr;
    uint32_t *xh, *xl, *wqh, *wql, *woh, *wol, *ah, *al;
    cudaGetSymbolAddress((void**)&qkv, g_qkv);
    cudaGetSymbolAddress((void**)&att, g_att);
    cudaGetSymbolAddress((void**)&xh,  g_xh);
    cudaGetSymbolAddress((void**)&xl,  g_xl);
    cudaGetSymbolAddress((void**)&wqh, g_wqh);
    cudaGetSymbolAddress((void**)&wql, g_wql);
    cudaGetSymbolAddress((void**)&woh, g_woh);
    cudaGetSymbolAddress((void**)&wol, g_wol);
    cudaGetSymbolAddress((void**)&ah,  g_ah);
    cudaGetSymbolAddress((void**)&al,  g_al);

    cudaFuncSetAttribute(attn_kernel, cudaFuncAttributeMaxDynamicSharedMemorySize, SMEM_ATTN);

    // 0) split inputs into bf16 hi/lo
    const int n2x = ROWS * KH;          // 4,194,304 pairs
    const int n2q = QKVD * KH;          // 1,572,864
    const int n2o = DIMX * KH;          // 524,288
    cvt_split<<<n2x / 256, 256>>>(x,    xh,  xl,  n2x);
    cvt_split<<<n2q / 256, 256>>>(Wqkv, wqh, wql, n2q);
    cvt_split<<<n2o / 256, 256>>>(Wout, woh, wol, n2o);

    // 1) qkv = x @ Wqkv^T   [8192,3072]
    dim3 g1(QKVD / 128, ROWS / 128);
    gemm_bf3<<<g1, 256>>>(xh, xl, wqh, wql, qkv, ROWS, QKVD, DIMX);

    // 2) causal attention -> g_att [8192,1024]
    dim3 g2(SEQ / 64, NH, BATCH);
    attn_kernel<<<g2, 256, SMEM_ATTN>>>();

    // 2b) split attention output
    cvt_split<<<n2x / 256, 256>>>(att, ah, al, n2x);

    // 3) out = att @ Wout^T [8192,1024]
    dim3 g3(DIMX / 128, ROWS / 128);
    gemm_bf3<<<g3, 256>>>(ah, al, woh, wol, out, ROWS, DIMX, DIMX);
}

// round 12
// speedup vs baseline: 1.9852x; 1.2094x over previous
#include <cuda_runtime.h>
#include <cstdint>

// ---------------------------------------------------------------------------
// Problem constants
// ---------------------------------------------------------------------------
#define DIMX   1024
#define NH     16
#define HD     64
#define BATCH  4
#define SEQ    2048
#define ROWS   (BATCH * SEQ)        // 8192
#define QKVD   (3 * DIMX)           // 3072
#define KH     (DIMX / 2)           // 512 u32 (bf16x2 pairs) per row

// ---------------------------------------------------------------------------
// Scratch (__device__ globals; allocation is forbidden)
// ---------------------------------------------------------------------------
__device__ float    g_qkv[(size_t)ROWS * QKVD];   // 96 MB (attention input, fp32)
__device__ float    g_att[(size_t)ROWS * DIMX];   // 32 MB (attention output, fp32)
__device__ uint32_t g_xh [(size_t)ROWS * KH];
__device__ uint32_t g_xl [(size_t)ROWS * KH];
__device__ uint32_t g_wqh[(size_t)QKVD * KH];
__device__ uint32_t g_wql[(size_t)QKVD * KH];
__device__ uint32_t g_woh[(size_t)DIMX * KH];
__device__ uint32_t g_wol[(size_t)DIMX * KH];
__device__ uint32_t g_ah [(size_t)ROWS * KH];
__device__ uint32_t g_al [(size_t)ROWS * KH];

// ---------------------------------------------------------------------------
// helpers
// ---------------------------------------------------------------------------
__device__ __forceinline__ void split2(float x, float y, uint32_t& h, uint32_t& l) {
    asm("cvt.rn.bf16x2.f32 %0, %1, %2;" : "=r"(h) : "f"(y), "f"(x));
    float hx = __uint_as_float(h << 16);
    float hy = __uint_as_float(h & 0xFFFF0000u);
    asm("cvt.rn.bf16x2.f32 %0, %1, %2;" : "=r"(l) : "f"(y - hy), "f"(x - hx));
}

__global__ __launch_bounds__(256)
void cvt_split(const float* __restrict__ src,
               uint32_t* __restrict__ hi, uint32_t* __restrict__ lo, int n2) {
    int i = blockIdx.x * blockDim.x + threadIdx.x;
    if (i >= n2) return;
    float2 v = ((const float2*)src)[i];
    uint32_t h, l;
    split2(v.x, v.y, h, l);
    hi[i] = h;
    lo[i] = l;
}

// mma.sync m16n8k16 bf16 (row.col), fp32 accumulate
__device__ __forceinline__ void mma_bf16(float* d, const uint32_t* a, const uint32_t* b) {
    asm volatile(
        "mma.sync.aligned.m16n8k16.row.col.f32.bf16.bf16.f32 "
        "{%0,%1,%2,%3}, {%4,%5,%6,%7}, {%8,%9}, {%0,%1,%2,%3};"
        : "+f"(d[0]), "+f"(d[1]), "+f"(d[2]), "+f"(d[3])
        : "r"(a[0]), "r"(a[1]), "r"(a[2]), "r"(a[3]), "r"(b[0]), "r"(b[1]));
}

// ---------------------------------------------------------------------------
// 3-term bf16 NT GEMM:  C[M,N] = A[M,K] * B[N,K]^T   (fp32 out)
// CTA 128x128, 256 threads (8 warps = 2x4), warp tile 64x32.
// Term order t1 (Ah.Bh) -> t3 (Ah.Bl, reuse A frags) -> t2 (Al.Bh): 56 LDS/chunk.
// ---------------------------------------------------------------------------
#define P_AH 0
#define P_AL 1024
#define P_BH 2048
#define P_BL 3072
#define BUFSZ 4096

__device__ __forceinline__ void stage_store(uint32_t* dst, uint32_t i0, uint32_t i1,
                                            uint4 v, int swp) {
    uint2 p0, p1;
    if (swp) { p0 = make_uint2(v.y, v.x); p1 = make_uint2(v.w, v.z); }
    else     { p0 = make_uint2(v.x, v.y); p1 = make_uint2(v.z, v.w); }
    *(uint2*)(dst + i0) = p0;
    *(uint2*)(dst + i1) = p1;
}

__global__ __launch_bounds__(256, 2)
void gemm_bf3(const uint32_t* __restrict__ Ah, const uint32_t* __restrict__ Al,
              const uint32_t* __restrict__ Bh, const uint32_t* __restrict__ Bl,
              float* __restrict__ C, int M, int N, int K) {
    __shared__ uint32_t smbuf[2 * BUFSZ];   // 32 KB

    const int tid   = threadIdx.x;
    const int lane  = tid & 31;
    const int wid   = tid >> 5;
    const int warpm = wid >> 2;
    const int warpn = wid & 3;
    const int g     = lane >> 2;
    const int tg    = lane & 3;
    const int bm    = blockIdx.y << 7;
    const int bn    = blockIdx.x << 7;
    const int KP    = K >> 1;

    const int srow  = tid >> 1;
    const int shalf = tid & 1;
    const int s     = srow & 7;
    const int swp   = s & 1;
    const uint32_t i0 = (uint32_t)srow * 8 + ((4 * shalf)     ^ (s & 6));
    const uint32_t i1 = (uint32_t)srow * 8 + ((4 * shalf + 2) ^ (s & 6));

    const uint32_t* pAh = Ah + (size_t)(bm + srow) * KP + shalf * 4;
    const uint32_t* pAl = Al + (size_t)(bm + srow) * KP + shalf * 4;
    const uint32_t* pBh = Bh + (size_t)(bn + srow) * KP + shalf * 4;
    const uint32_t* pBl = Bl + (size_t)(bn + srow) * KP + shalf * 4;

    float acc[4][4][4];
#pragma unroll
    for (int i = 0; i < 4; i++)
#pragma unroll
        for (int j = 0; j < 4; j++)
#pragma unroll
            for (int q = 0; q < 4; q++) acc[i][j][q] = 0.f;

    const int nt = K >> 4;

    uint4 vah = *(const uint4*)(pAh);
    uint4 val = *(const uint4*)(pAl);
    uint4 vbh = *(const uint4*)(pBh);
    uint4 vbl = *(const uint4*)(pBl);
    stage_store(smbuf + P_AH, i0, i1, vah, swp);
    stage_store(smbuf + P_AL, i0, i1, val, swp);
    stage_store(smbuf + P_BH, i0, i1, vbh, swp);
    stage_store(smbuf + P_BL, i0, i1, vbl, swp);
    __syncthreads();

    const int c0 = tg ^ g;
    const int c1 = (tg + 4) ^ g;

    for (int t = 0; t < nt; t++) {
        const uint32_t* S = smbuf + (t & 1) * BUFSZ;

        if (t + 1 < nt) {
            vah = *(const uint4*)(pAh + (t + 1) * 8);
            val = *(const uint4*)(pAl + (t + 1) * 8);
            vbh = *(const uint4*)(pBh + (t + 1) * 8);
            vbl = *(const uint4*)(pBl + (t + 1) * 8);
        }

        uint32_t a[4][4], b[4][2];

        // ---- t1: Ah * Bh ----
#pragma unroll
        for (int i = 0; i < 4; i++) {
            int r = warpm * 64 + i * 16 + g;
            a[i][0] = S[P_AH + r * 8 + c0];
            a[i][1] = S[P_AH + (r + 8) * 8 + c0];
            a[i][2] = S[P_AH + r * 8 + c1];
            a[i][3] = S[P_AH + (r + 8) * 8 + c1];
        }
#pragma unroll
        for (int j = 0; j < 4; j++) {
            int n = warpn * 32 + j * 8 + g;
            b[j][0] = S[P_BH + n * 8 + c0];
            b[j][1] = S[P_BH + n * 8 + c1];
        }
#pragma unroll
        for (int i = 0; i < 4; i++)
#pragma unroll
            for (int j = 0; j < 4; j++) mma_bf16(acc[i][j], a[i], b[j]);

        // ---- t3: Ah * Bl (reuse a) ----
#pragma unroll
        for (int j = 0; j < 4; j++) {
            int n = warpn * 32 + j * 8 + g;
            b[j][0] = S[P_BL + n * 8 + c0];
            b[j][1] = S[P_BL + n * 8 + c1];
        }
#pragma unroll
        for (int i = 0; i < 4; i++)
#pragma unroll
            for (int j = 0; j < 4; j++) mma_bf16(acc[i][j], a[i], b[j]);

        // ---- t2: Al * Bh ----
#pragma unroll
        for (int i = 0; i < 4; i++) {
            int r = warpm * 64 + i * 16 + g;
            a[i][0] = S[P_AL + r * 8 + c0];
            a[i][1] = S[P_AL + (r + 8) * 8 + c0];
            a[i][2] = S[P_AL + r * 8 + c1];
            a[i][3] = S[P_AL + (r + 8) * 8 + c1];
        }
#pragma unroll
        for (int j = 0; j < 4; j++) {
            int n = warpn * 32 + j * 8 + g;
            b[j][0] = S[P_BH + n * 8 + c0];
            b[j][1] = S[P_BH + n * 8 + c1];
        }
#pragma unroll
        for (int i = 0; i < 4; i++)
#pragma unroll
            for (int j = 0; j < 4; j++) mma_bf16(acc[i][j], a[i], b[j]);

        if (t + 1 < nt) {
            uint32_t* D = smbuf + ((t + 1) & 1) * BUFSZ;
            stage_store(D + P_AH, i0, i1, vah, swp);
            stage_store(D + P_AL, i0, i1, val, swp);
            stage_store(D + P_BH, i0, i1, vbh, swp);
            stage_store(D + P_BL, i0, i1, vbl, swp);
        }
        __syncthreads();
    }

#pragma unroll
    for (int i = 0; i < 4; i++) {
        int row = bm + warpm * 64 + i * 16 + g;
#pragma unroll
        for (int j = 0; j < 4; j++) {
            int col = bn + warpn * 32 + j * 8 + 2 * tg;
            *(float2*)&C[(size_t)row * N + col]       = make_float2(acc[i][j][0], acc[i][j][1]);
            *(float2*)&C[(size_t)(row + 8) * N + col] = make_float2(acc[i][j][2], acc[i][j][3]);
        }
    }
}

// ---------------------------------------------------------------------------
// Causal flash attention with mma.sync, 3-term bf16 compensation.
// CTA: 128 threads (4 warps), 64 q-rows, one (b,h). Warp = 16 rows x 64 keys.
// Q/K split hi/lo in smem (bf16x2, XOR swizzle); V fp32 transposed [d][key].
// S accumulator fragments re-packed directly as A-fragments for PV.
// smem = 32KB (Qh/Ql/Kh/Kl) + 64*66*4 (Vt) = 49664 B dynamic.
// ---------------------------------------------------------------------------
#define VT_PITCH 66
#define AT_SMEM  (32768 + 64 * VT_PITCH * 4)

__global__ __launch_bounds__(128, 3)
void attn_mma() {
    extern __shared__ uint32_t sm[];
    uint32_t* Qh = sm;              // 4 chunks x [64][8]
    uint32_t* Ql = sm + 2048;
    uint32_t* Kh = sm + 4096;
    uint32_t* Kl = sm + 6144;
    float*    Vt = (float*)(sm + 8192);   // [64][VT_PITCH]

    const int tid  = threadIdx.x;
    const int lane = tid & 31;
    const int wid  = tid >> 5;
    const int g    = lane >> 2;
    const int tg   = lane & 3;
    const int rb   = wid << 4;          // warp row base (0,16,32,48)
    const int qb   = blockIdx.x;
    const int h    = blockIdx.y;
    const int b    = blockIdx.z;

    const int srow = tid >> 1;          // 0..63
    const int shf  = tid & 1;
    const int s    = srow & 7;

    // ---- stage Q (scaled), split hi/lo ----
    {
        const float* gq = g_qkv + ((size_t)(b * SEQ + qb * 64 + srow)) * QKVD + h * HD + shf * 32;
#pragma unroll
        for (int i = 0; i < 8; i++) {
            float4 v = *(const float4*)(gq + i * 4);
            v.x *= 0.125f; v.y *= 0.125f; v.z *= 0.125f; v.w *= 0.125f;
            int c  = shf * 2 + (i >> 2);
            int kp = (i & 3) * 2;
            uint32_t h0, l0, h1, l1;
            split2(v.x, v.y, h0, l0);
            split2(v.z, v.w, h1, l1);
            int base = c * 512 + srow * 8;
            Qh[base + (kp ^ s)]       = h0;
            Qh[base + ((kp + 1) ^ s)] = h1;
            Ql[base + (kp ^ s)]       = l0;
            Ql[base + ((kp + 1) ^ s)] = l1;
        }
    }

    float m0 = -1e30f, m1 = -1e30f, l0s = 0.f, l1s = 0.f;
    float oacc[8][4];
#pragma unroll
    for (int j = 0; j < 8; j++)
#pragma unroll
        for (int q = 0; q < 4; q++) oacc[j][q] = 0.f;

    const int c0 = tg ^ g;
    const int c1 = (tg + 4) ^ g;

    for (int kb = 0; kb <= qb; kb++) {
        __syncthreads();   // previous iteration done reading K/V (also covers Q staging)

        // ---- stage K (split) and V (fp32 transposed) ----
        {
            const float* gk = g_qkv + ((size_t)(b * SEQ + kb * 64 + srow)) * QKVD + DIMX + h * HD + shf * 32;
            const float* gv = gk + DIMX;
#pragma unroll
            for (int i = 0; i < 8; i++) {
                float4 v = *(const float4*)(gk + i * 4);
                int c  = shf * 2 + (i >> 2);
                int kp = (i & 3) * 2;
                uint32_t h0, l0, h1, l1;
                split2(v.x, v.y, h0, l0);
                split2(v.z, v.w, h1, l1);
                int base = c * 512 + srow * 8;
                Kh[base + (kp ^ s)]       = h0;
                Kh[base + ((kp + 1) ^ s)] = h1;
                Kl[base + (kp ^ s)]       = l0;
                Kl[base + ((kp + 1) ^ s)] = l1;

                float4 vv = *(const float4*)(gv + i * 4);
                int d0 = shf * 32 + i * 4;
                Vt[(d0 + 0) * VT_PITCH + srow] = vv.x;
                Vt[(d0 + 1) * VT_PITCH + srow] = vv.y;
                Vt[(d0 + 2) * VT_PITCH + srow] = vv.z;
                Vt[(d0 + 3) * VT_PITCH + srow] = vv.w;
            }
        }
        __syncthreads();

        // ---- S = Q K^T, 3-term ----
        float sacc[8][4];
#pragma unroll
        for (int j = 0; j < 8; j++)
#pragma unroll
            for (int q = 0; q < 4; q++) sacc[j][q] = 0.f;

#pragma unroll
        for (int c = 0; c < 4; c++) {
            uint32_t a[4], bb[8][2];
            const int ab  = c * 512 + (rb + g) * 8;
            const int ab8 = c * 512 + (rb + g + 8) * 8;
            // t1: Qh.Kh
            a[0] = Qh[ab + c0];  a[1] = Qh[ab8 + c0];
            a[2] = Qh[ab + c1];  a[3] = Qh[ab8 + c1];
#pragma unroll
            for (int j = 0; j < 8; j++) {
                int nb = c * 512 + (j * 8 + g) * 8;
                bb[j][0] = Kh[nb + c0];
                bb[j][1] = Kh[nb + c1];
            }
#pragma unroll
            for (int j = 0; j < 8; j++) mma_bf16(sacc[j], a, bb[j]);
            // t3: Qh.Kl (reuse a)
#pragma unroll
            for (int j = 0; j < 8; j++) {
                int nb = c * 512 + (j * 8 + g) * 8;
                bb[j][0] = Kl[nb + c0];
                bb[j][1] = Kl[nb + c1];
            }
#pragma unroll
            for (int j = 0; j < 8; j++) mma_bf16(sacc[j], a, bb[j]);
            // t2: Ql.Kh
            a[0] = Ql[ab + c0];  a[1] = Ql[ab8 + c0];
            a[2] = Ql[ab + c1];  a[3] = Ql[ab8 + c1];
#pragma unroll
            for (int j = 0; j < 8; j++) {
                int nb = c * 512 + (j * 8 + g) * 8;
                bb[j][0] = Kh[nb + c0];
                bb[j][1] = Kh[nb + c1];
            }
#pragma unroll
            for (int j = 0; j < 8; j++) mma_bf16(sacc[j], a, bb[j]);
        }

        // ---- causal mask on diagonal block ----
        if (kb == qb) {
            const int r0 = rb + g, r1 = rb + g + 8;
#pragma unroll
            for (int j = 0; j < 8; j++) {
                int col = j * 8 + 2 * tg;
                if (col     > r0) sacc[j][0] = -1e30f;
                if (col + 1 > r0) sacc[j][1] = -1e30f;
                if (col     > r1) sacc[j][2] = -1e30f;
                if (col + 1 > r1) sacc[j][3] = -1e30f;
            }
        }

        // ---- online softmax (rows g and g+8; quad shares a row) ----
        float mx0 = -1e30f, mx1 = -1e30f;
#pragma unroll
        for (int j = 0; j < 8; j++) {
            mx0 = fmaxf(mx0, fmaxf(sacc[j][0], sacc[j][1]));
            mx1 = fmaxf(mx1, fmaxf(sacc[j][2], sacc[j][3]));
        }
        mx0 = fmaxf(mx0, __shfl_xor_sync(0xffffffffu, mx0, 1));
        mx0 = fmaxf(mx0, __shfl_xor_sync(0xffffffffu, mx0, 2));
        mx1 = fmaxf(mx1, __shfl_xor_sync(0xffffffffu, mx1, 1));
        mx1 = fmaxf(mx1, __shfl_xor_sync(0xffffffffu, mx1, 2));

        float mn0 = fmaxf(m0, mx0), mn1 = fmaxf(m1, mx1);
        float al0 = __expf(m0 - mn0), al1 = __expf(m1 - mn1);
        m0 = mn0; m1 = mn1;

        float rs0 = 0.f, rs1 = 0.f;
#pragma unroll
        for (int j = 0; j < 8; j++) {
            sacc[j][0] = __expf(sacc[j][0] - mn0); rs0 += sacc[j][0];
            sacc[j][1] = __expf(sacc[j][1] - mn0); rs0 += sacc[j][1];
            sacc[j][2] = __expf(sacc[j][2] - mn1); rs1 += sacc[j][2];
            sacc[j][3] = __expf(sacc[j][3] - mn1); rs1 += sacc[j][3];
        }
        rs0 += __shfl_xor_sync(0xffffffffu, rs0, 1);
        rs0 += __shfl_xor_sync(0xffffffffu, rs0, 2);
        rs1 += __shfl_xor_sync(0xffffffffu, rs1, 1);
        rs1 += __shfl_xor_sync(0xffffffffu, rs1, 2);
        l0s = l0s * al0 + rs0;
        l1s = l1s * al1 + rs1;

#pragma unroll
        for (int j = 0; j < 8; j++) {
            oacc[j][0] *= al0; oacc[j][1] *= al0;
            oacc[j][2] *= al1; oacc[j][3] *= al1;
        }

        // ---- O += P V, 3-term; P straight from S fragments ----
#pragma unroll
        for (int cc = 0; cc < 4; cc++) {
            uint32_t ph[4], pl[4];
            split2(sacc[2 * cc][0],     sacc[2 * cc][1],     ph[0], pl[0]);
            split2(sacc[2 * cc][2],     sacc[2 * cc][3],     ph[1], pl[1]);
            split2(sacc[2 * cc + 1][0], sacc[2 * cc + 1][1], ph[2], pl[2]);
            split2(sacc[2 * cc + 1][2], sacc[2 * cc + 1][3], ph[3], pl[3]);
#pragma unroll
            for (int j2 = 0; j2 < 8; j2++) {
                const float* vp = Vt + (j2 * 8 + g) * VT_PITCH + cc * 16 + 2 * tg;
                float2 f0 = *(const float2*)(vp);
                float2 f1 = *(const float2*)(vp + 8);
                uint32_t vh[2], vl[2];
                split2(f0.x, f0.y, vh[0], vl[0]);
                split2(f1.x, f1.y, vh[1], vl[1]);
                mma_bf16(oacc[j2], ph, vh);
                mma_bf16(oacc[j2], pl, vh);
                mma_bf16(oacc[j2], ph, vl);
            }
        }
    }

    // ---- finalize ----
    const float inv0 = 1.0f / l0s, inv1 = 1.0f / l1s;
    float* go = g_att + ((size_t)(b * SEQ + qb * 64 + rb + g)) * DIMX + h * HD;
    float* go8 = go + (size_t)8 * DIMX;
#pragma unroll
    for (int j2 = 0; j2 < 8; j2++) {
        int col = j2 * 8 + 2 * tg;
        *(float2*)(go  + col) = make_float2(oacc[j2][0] * inv0, oacc[j2][1] * inv0);
        *(float2*)(go8 + col) = make_float2(oacc[j2][2] * inv1, oacc[j2][3] * inv1);
    }
}

// ---------------------------------------------------------------------------
// launch
// ---------------------------------------------------------------------------
extern "C" void kernel_launch(void* const* d_in, const int* in_sizes, int n_in,
                              void* d_out, int out_size) {
    const float* x    = (const float*)d_in[0];   // [4,2048,1024]
    const float* Wqkv = (const float*)d_in[1];   // [3072,1024]
    const float* Wout = (const float*)d_in[2];   // [1024,1024]
    float*       out  = (float*)d_out;           // [4,2048,1024]

    float *qkv = nullptr, *att = nullptr;
    uint32_t *xh, *xl, *wqh, *wql, *woh, *wol, *ah, *al;
    cudaGetSymbolAddress((void**)&qkv, g_qkv);
    cudaGetSymbolAddress((void**)&att, g_att);
    cudaGetSymbolAddress((void**)&xh,  g_xh);
    cudaGetSymbolAddress((void**)&xl,  g_xl);
    cudaGetSymbolAddress((void**)&wqh, g_wqh);
    cudaGetSymbolAddress((void**)&wql, g_wql);
    cudaGetSymbolAddress((void**)&woh, g_woh);
    cudaGetSymbolAddress((void**)&wol, g_wol);
    cudaGetSymbolAddress((void**)&ah,  g_ah);
    cudaGetSymbolAddress((void**)&al,  g_al);

    cudaFuncSetAttribute(attn_mma, cudaFuncAttributeMaxDynamicSharedMemorySize, AT_SMEM);

    // 0) split inputs into bf16 hi/lo
    const int n2x = ROWS * KH;
    const int n2q = QKVD * KH;
    const int n2o = DIMX * KH;
    cvt_split<<<n2x / 256, 256>>>(x,    xh,  xl,  n2x);
    cvt_split<<<n2q / 256, 256>>>(Wqkv, wqh, wql, n2q);
    cvt_split<<<n2o / 256, 256>>>(Wout, woh, wol, n2o);

    // 1) qkv = x @ Wqkv^T   [8192,3072]
    dim3 g1(QKVD / 128, ROWS / 128);
    gemm_bf3<<<g1, 256>>>(xh, xl, wqh, wql, qkv, ROWS, QKVD, DIMX);

    // 2) causal attention -> g_att [8192,1024]
    dim3 g2(SEQ / 64, NH, BATCH);
    attn_mma<<<g2, 128, AT_SMEM>>>();

    // 2b) split attention output
    cvt_split<<<n2x / 256, 256>>>(att, ah, al, n2x);

    // 3) out = att @ Wout^T [8192,1024]
    dim3 g3(DIMX / 128, ROWS / 128);
    gemm_bf3<<<g3, 256>>>(ah, al, woh, wol, out, ROWS, DIMX, DIMX);
}

// round 13
// speedup vs baseline: 2.3874x; 1.2026x over previous
#include <cuda_runtime.h>
#include <cstdint>

// ---------------------------------------------------------------------------
// Problem constants
// ---------------------------------------------------------------------------
#define DIMX   1024
#define NH     16
#define HD     64
#define BATCH  4
#define SEQ    2048
#define ROWS   (BATCH * SEQ)        // 8192
#define QKVD   (3 * DIMX)           // 3072
#define KH     (DIMX / 2)           // 512 u32 pairs per 1024 cols
#define KQ     (QKVD / 2)           // 1536 u32 pairs per qkv row

// ---------------------------------------------------------------------------
// Scratch (__device__ globals; allocation is forbidden)
// ---------------------------------------------------------------------------
__device__ float    g_qkv [(size_t)ROWS * QKVD];   // 96 MB fp32 qkv
__device__ uint32_t g_qkvh[(size_t)ROWS * KQ];     // qkv hi (Q pre-scaled)
__device__ uint32_t g_qkvl[(size_t)ROWS * KQ];     // qkv lo
__device__ uint32_t g_vth [(size_t)BATCH * NH * HD * (SEQ / 2)];  // V^T hi
__device__ uint32_t g_vtl [(size_t)BATCH * NH * HD * (SEQ / 2)];  // V^T lo
__device__ uint32_t g_xh  [(size_t)ROWS * KH];
__device__ uint32_t g_xl  [(size_t)ROWS * KH];
__device__ uint32_t g_wqh [(size_t)QKVD * KH];
__device__ uint32_t g_wql [(size_t)QKVD * KH];
__device__ uint32_t g_woh [(size_t)DIMX * KH];
__device__ uint32_t g_wol [(size_t)DIMX * KH];
__device__ uint32_t g_ah  [(size_t)ROWS * KH];     // attention out hi
__device__ uint32_t g_al  [(size_t)ROWS * KH];     // attention out lo

// ---------------------------------------------------------------------------
// helpers
// ---------------------------------------------------------------------------
__device__ __forceinline__ void split2(float x, float y, uint32_t& h, uint32_t& l) {
    asm("cvt.rn.bf16x2.f32 %0, %1, %2;" : "=r"(h) : "f"(y), "f"(x));
    float hx = __uint_as_float(h << 16);
    float hy = __uint_as_float(h & 0xFFFF0000u);
    asm("cvt.rn.bf16x2.f32 %0, %1, %2;" : "=r"(l) : "f"(y - hy), "f"(x - hx));
}

__global__ __launch_bounds__(256)
void cvt_split(const float* __restrict__ src,
               uint32_t* __restrict__ hi, uint32_t* __restrict__ lo, int n2) {
    int i = blockIdx.x * blockDim.x + threadIdx.x;
    if (i >= n2) return;
    float2 v = ((const float2*)src)[i];
    uint32_t h, l;
    split2(v.x, v.y, h, l);
    hi[i] = h;
    lo[i] = l;
}

// split whole qkv rows; Q section (first 512 pairs) pre-scaled by 0.125
__global__ __launch_bounds__(256)
void cvt_qkv() {
    int i = blockIdx.x * 256 + threadIdx.x;          // < ROWS*KQ
    int c = i % KQ;
    float2 v = ((const float2*)g_qkv)[i];
    float sc = (c < 512) ? 0.125f : 1.0f;
    uint32_t h, l;
    split2(v.x * sc, v.y * sc, h, l);
    g_qkvh[i] = h;
    g_qkvl[i] = l;
}

// V^T split: out [b*NH+h][d][SEQ/2 pairs], pairs packed along key (token)
__global__ __launch_bounds__(256)
void cvt_vT() {
    __shared__ float tile[32][65];
    const int bh = blockIdx.y;          // b*NH + h
    const int b  = bh >> 4, h = bh & 15;
    const int t0 = blockIdx.x * 32;
    const int tid = threadIdx.x;
#pragma unroll
    for (int r = 0; r < 8; r++) {
        int e  = r * 256 + tid;
        int ti = e >> 6, d = e & 63;
        tile[ti][d] = g_qkv[(size_t)(b * SEQ + t0 + ti) * QKVD + 2 * DIMX + h * HD + d];
    }
    __syncthreads();
    const int d  = tid >> 2;
    const int pg = (tid & 3) * 4;
    size_t obase = ((size_t)bh * HD + d) * (SEQ / 2) + (t0 >> 1) + pg;
#pragma unroll
    for (int p = 0; p < 4; p++) {
        uint32_t hh, ll;
        split2(tile[2 * (pg + p)][d], tile[2 * (pg + p) + 1][d], hh, ll);
        g_vth[obase + p] = hh;
        g_vtl[obase + p] = ll;
    }
}

// mma.sync m16n8k16 bf16 (row.col), fp32 accumulate
__device__ __forceinline__ void mma_bf16(float* d, const uint32_t* a, const uint32_t* b) {
    asm volatile(
        "mma.sync.aligned.m16n8k16.row.col.f32.bf16.bf16.f32 "
        "{%0,%1,%2,%3}, {%4,%5,%6,%7}, {%8,%9}, {%0,%1,%2,%3};"
        : "+f"(d[0]), "+f"(d[1]), "+f"(d[2]), "+f"(d[3])
        : "r"(a[0]), "r"(a[1]), "r"(a[2]), "r"(a[3]), "r"(b[0]), "r"(b[1]));
}

// ---------------------------------------------------------------------------
// 3-term bf16 NT GEMM (unchanged from R12)
// ---------------------------------------------------------------------------
#define P_AH 0
#define P_AL 1024
#define P_BH 2048
#define P_BL 3072
#define BUFSZ 4096

__device__ __forceinline__ void stage_store(uint32_t* dst, uint32_t i0, uint32_t i1,
                                            uint4 v, int swp) {
    uint2 p0, p1;
    if (swp) { p0 = make_uint2(v.y, v.x); p1 = make_uint2(v.w, v.z); }
    else     { p0 = make_uint2(v.x, v.y); p1 = make_uint2(v.z, v.w); }
    *(uint2*)(dst + i0) = p0;
    *(uint2*)(dst + i1) = p1;
}

__global__ __launch_bounds__(256, 2)
void gemm_bf3(const uint32_t* __restrict__ Ah, const uint32_t* __restrict__ Al,
              const uint32_t* __restrict__ Bh, const uint32_t* __restrict__ Bl,
              float* __restrict__ C, int M, int N, int K) {
    __shared__ uint32_t smbuf[2 * BUFSZ];

    const int tid   = threadIdx.x;
    const int lane  = tid & 31;
    const int wid   = tid >> 5;
    const int warpm = wid >> 2;
    const int warpn = wid & 3;
    const int g     = lane >> 2;
    const int tg    = lane & 3;
    const int bm    = blockIdx.y << 7;
    const int bn    = blockIdx.x << 7;
    const int KP    = K >> 1;

    const int srow  = tid >> 1;
    const int shalf = tid & 1;
    const int s     = srow & 7;
    const int swp   = s & 1;
    const uint32_t i0 = (uint32_t)srow * 8 + ((4 * shalf)     ^ (s & 6));
    const uint32_t i1 = (uint32_t)srow * 8 + ((4 * shalf + 2) ^ (s & 6));

    const uint32_t* pAh = Ah + (size_t)(bm + srow) * KP + shalf * 4;
    const uint32_t* pAl = Al + (size_t)(bm + srow) * KP + shalf * 4;
    const uint32_t* pBh = Bh + (size_t)(bn + srow) * KP + shalf * 4;
    const uint32_t* pBl = Bl + (size_t)(bn + srow) * KP + shalf * 4;

    float acc[4][4][4];
#pragma unroll
    for (int i = 0; i < 4; i++)
#pragma unroll
        for (int j = 0; j < 4; j++)
#pragma unroll
            for (int q = 0; q < 4; q++) acc[i][j][q] = 0.f;

    const int nt = K >> 4;

    uint4 vah = *(const uint4*)(pAh);
    uint4 val = *(const uint4*)(pAl);
    uint4 vbh = *(const uint4*)(pBh);
    uint4 vbl = *(const uint4*)(pBl);
    stage_store(smbuf + P_AH, i0, i1, vah, swp);
    stage_store(smbuf + P_AL, i0, i1, val, swp);
    stage_store(smbuf + P_BH, i0, i1, vbh, swp);
    stage_store(smbuf + P_BL, i0, i1, vbl, swp);
    __syncthreads();

    const int c0 = tg ^ g;
    const int c1 = (tg + 4) ^ g;

    for (int t = 0; t < nt; t++) {
        const uint32_t* S = smbuf + (t & 1) * BUFSZ;

        if (t + 1 < nt) {
            vah = *(const uint4*)(pAh + (t + 1) * 8);
            val = *(const uint4*)(pAl + (t + 1) * 8);
            vbh = *(const uint4*)(pBh + (t + 1) * 8);
            vbl = *(const uint4*)(pBl + (t + 1) * 8);
        }

        uint32_t a[4][4], b[4][2];

        // t1: Ah * Bh
#pragma unroll
        for (int i = 0; i < 4; i++) {
            int r = warpm * 64 + i * 16 + g;
            a[i][0] = S[P_AH + r * 8 + c0];
            a[i][1] = S[P_AH + (r + 8) * 8 + c0];
            a[i][2] = S[P_AH + r * 8 + c1];
            a[i][3] = S[P_AH + (r + 8) * 8 + c1];
        }
#pragma unroll
        for (int j = 0; j < 4; j++) {
            int n = warpn * 32 + j * 8 + g;
            b[j][0] = S[P_BH + n * 8 + c0];
            b[j][1] = S[P_BH + n * 8 + c1];
        }
#pragma unroll
        for (int i = 0; i < 4; i++)
#pragma unroll
            for (int j = 0; j < 4; j++) mma_bf16(acc[i][j], a[i], b[j]);

        // t3: Ah * Bl (reuse a)
#pragma unroll
        for (int j = 0; j < 4; j++) {
            int n = warpn * 32 + j * 8 + g;
            b[j][0] = S[P_BL + n * 8 + c0];
            b[j][1] = S[P_BL + n * 8 + c1];
        }
#pragma unroll
        for (int i = 0; i < 4; i++)
#pragma unroll
            for (int j = 0; j < 4; j++) mma_bf16(acc[i][j], a[i], b[j]);

        // t2: Al * Bh
#pragma unroll
        for (int i = 0; i < 4; i++) {
            int r = warpm * 64 + i * 16 + g;
            a[i][0] = S[P_AL + r * 8 + c0];
            a[i][1] = S[P_AL + (r + 8) * 8 + c0];
            a[i][2] = S[P_AL + r * 8 + c1];
            a[i][3] = S[P_AL + (r + 8) * 8 + c1];
        }
#pragma unroll
        for (int j = 0; j < 4; j++) {
            int n = warpn * 32 + j * 8 + g;
            b[j][0] = S[P_BH + n * 8 + c0];
            b[j][1] = S[P_BH + n * 8 + c1];
        }
#pragma unroll
        for (int i = 0; i < 4; i++)
#pragma unroll
            for (int j = 0; j < 4; j++) mma_bf16(acc[i][j], a[i], b[j]);

        if (t + 1 < nt) {
            uint32_t* D = smbuf + ((t + 1) & 1) * BUFSZ;
            stage_store(D + P_AH, i0, i1, vah, swp);
            stage_store(D + P_AL, i0, i1, val, swp);
            stage_store(D + P_BH, i0, i1, vbh, swp);
            stage_store(D + P_BL, i0, i1, vbl, swp);
        }
        __syncthreads();
    }

#pragma unroll
    for (int i = 0; i < 4; i++) {
        int row = bm + warpm * 64 + i * 16 + g;
#pragma unroll
        for (int j = 0; j < 4; j++) {
            int col = bn + warpn * 32 + j * 8 + 2 * tg;
            *(float2*)&C[(size_t)row * N + col]       = make_float2(acc[i][j][0], acc[i][j][1]);
            *(float2*)&C[(size_t)(row + 8) * N + col] = make_float2(acc[i][j][2], acc[i][j][3]);
        }
    }
}

// ---------------------------------------------------------------------------
// Causal flash attention, mma.sync, all operands pre-split in gmem.
// CTA: 128 threads (4 warps), 64 q-rows, one (b,h). Warp = 16 rows x 64 keys.
// smem u32: Qh[2048] Ql[2048] Kh[2048] Kl[2048] Vh[2304] Vl[2304] = 51200 B.
// V smem pitch 36 -> PV B-frag LDS bank = 4g+tg (conflict-free).
// Epilogue writes bf16x2 hi/lo (g_ah/g_al) directly for GEMM2.
// ---------------------------------------------------------------------------
#define AT_SMEM (12800 * 4)

__global__ __launch_bounds__(128, 3)
void attn_mma() {
    extern __shared__ uint32_t sm[];
    uint32_t* Qh = sm;
    uint32_t* Ql = sm + 2048;
    uint32_t* Kh = sm + 4096;
    uint32_t* Kl = sm + 6144;
    uint32_t* Vh = sm + 8192;
    uint32_t* Vl = sm + 10496;

    const int tid  = threadIdx.x;
    const int lane = tid & 31;
    const int wid  = tid >> 5;
    const int g    = lane >> 2;
    const int tg   = lane & 3;
    const int rb   = wid << 4;
    const int qb   = blockIdx.x;
    const int h    = blockIdx.y;
    const int b    = blockIdx.z;

    const int srow = tid >> 1;
    const int shf  = tid & 1;
    const int s    = srow & 7;

    // ---- stage Q (pre-scaled hi/lo from gmem) ----
    {
        size_t base = (size_t)(b * SEQ + qb * 64 + srow) * KQ + h * 32 + shf * 16;
#pragma unroll
        for (int i = 0; i < 4; i++) {
            uint4 vh4 = *(const uint4*)(g_qkvh + base + i * 4);
            uint4 vl4 = *(const uint4*)(g_qkvl + base + i * 4);
            int p0 = shf * 16 + i * 4;
            int sbase = ((p0 >> 3) * 64 + srow) * 8;
            int kp = p0 & 7;
            Qh[sbase + ((kp + 0) ^ s)] = vh4.x;
            Qh[sbase + ((kp + 1) ^ s)] = vh4.y;
            Qh[sbase + ((kp + 2) ^ s)] = vh4.z;
            Qh[sbase + ((kp + 3) ^ s)] = vh4.w;
            Ql[sbase + ((kp + 0) ^ s)] = vl4.x;
            Ql[sbase + ((kp + 1) ^ s)] = vl4.y;
            Ql[sbase + ((kp + 2) ^ s)] = vl4.z;
            Ql[sbase + ((kp + 3) ^ s)] = vl4.w;
        }
    }

    float m0 = -1e30f, m1 = -1e30f, l0s = 0.f, l1s = 0.f;
    float oacc[8][4];
#pragma unroll
    for (int j = 0; j < 8; j++)
#pragma unroll
        for (int q = 0; q < 4; q++) oacc[j][q] = 0.f;

    const int c0 = tg ^ g;
    const int c1 = (tg + 4) ^ g;

    for (int kb = 0; kb <= qb; kb++) {
        __syncthreads();

        // ---- stage K hi/lo ----
        {
            size_t base = (size_t)(b * SEQ + kb * 64 + srow) * KQ + 512 + h * 32 + shf * 16;
#pragma unroll
            for (int i = 0; i < 4; i++) {
                uint4 vh4 = *(const uint4*)(g_qkvh + base + i * 4);
                uint4 vl4 = *(const uint4*)(g_qkvl + base + i * 4);
                int p0 = shf * 16 + i * 4;
                int sbase = ((p0 >> 3) * 64 + srow) * 8;
                int kp = p0 & 7;
                Kh[sbase + ((kp + 0) ^ s)] = vh4.x;
                Kh[sbase + ((kp + 1) ^ s)] = vh4.y;
                Kh[sbase + ((kp + 2) ^ s)] = vh4.z;
                Kh[sbase + ((kp + 3) ^ s)] = vh4.w;
                Kl[sbase + ((kp + 0) ^ s)] = vl4.x;
                Kl[sbase + ((kp + 1) ^ s)] = vl4.y;
                Kl[sbase + ((kp + 2) ^ s)] = vl4.z;
                Kl[sbase + ((kp + 3) ^ s)] = vl4.w;
            }
        }
        // ---- stage V^T hi/lo (pairs along key) ----
        {
            size_t vbase = ((size_t)(b * NH + h) * HD + srow) * (SEQ / 2) + kb * 32 + shf * 16;
            int d36 = srow * 36 + shf * 16;
#pragma unroll
            for (int i = 0; i < 4; i++) {
                *(uint4*)(Vh + d36 + i * 4) = *(const uint4*)(g_vth + vbase + i * 4);
                *(uint4*)(Vl + d36 + i * 4) = *(const uint4*)(g_vtl + vbase + i * 4);
            }
        }
        __syncthreads();

        // ---- S = Q K^T, 3-term ----
        float sacc[8][4];
#pragma unroll
        for (int j = 0; j < 8; j++)
#pragma unroll
            for (int q = 0; q < 4; q++) sacc[j][q] = 0.f;

#pragma unroll
        for (int c = 0; c < 4; c++) {
            uint32_t a[4], bb[8][2];
            const int ab  = c * 512 + (rb + g) * 8;
            const int ab8 = c * 512 + (rb + g + 8) * 8;
            a[0] = Qh[ab + c0];  a[1] = Qh[ab8 + c0];
            a[2] = Qh[ab + c1];  a[3] = Qh[ab8 + c1];
#pragma unroll
            for (int j = 0; j < 8; j++) {
                int nb = c * 512 + (j * 8 + g) * 8;
                bb[j][0] = Kh[nb + c0];
                bb[j][1] = Kh[nb + c1];
            }
#pragma unroll
            for (int j = 0; j < 8; j++) mma_bf16(sacc[j], a, bb[j]);
#pragma unroll
            for (int j = 0; j < 8; j++) {
                int nb = c * 512 + (j * 8 + g) * 8;
                bb[j][0] = Kl[nb + c0];
                bb[j][1] = Kl[nb + c1];
            }
#pragma unroll
            for (int j = 0; j < 8; j++) mma_bf16(sacc[j], a, bb[j]);
            a[0] = Ql[ab + c0];  a[1] = Ql[ab8 + c0];
            a[2] = Ql[ab + c1];  a[3] = Ql[ab8 + c1];
#pragma unroll
            for (int j = 0; j < 8; j++) {
                int nb = c * 512 + (j * 8 + g) * 8;
                bb[j][0] = Kh[nb + c0];
                bb[j][1] = Kh[nb + c1];
            }
#pragma unroll
            for (int j = 0; j < 8; j++) mma_bf16(sacc[j], a, bb[j]);
        }

        // ---- causal mask on diagonal block ----
        if (kb == qb) {
            const int r0 = rb + g, r1 = rb + g + 8;
#pragma unroll
            for (int j = 0; j < 8; j++) {
                int col = j * 8 + 2 * tg;
                if (col     > r0) sacc[j][0] = -1e30f;
                if (col + 1 > r0) sacc[j][1] = -1e30f;
                if (col     > r1) sacc[j][2] = -1e30f;
                if (col + 1 > r1) sacc[j][3] = -1e30f;
            }
        }

        // ---- online softmax ----
        float mx0 = -1e30f, mx1 = -1e30f;
#pragma unroll
        for (int j = 0; j < 8; j++) {
            mx0 = fmaxf(mx0, fmaxf(sacc[j][0], sacc[j][1]));
            mx1 = fmaxf(mx1, fmaxf(sacc[j][2], sacc[j][3]));
        }
        mx0 = fmaxf(mx0, __shfl_xor_sync(0xffffffffu, mx0, 1));
        mx0 = fmaxf(mx0, __shfl_xor_sync(0xffffffffu, mx0, 2));
        mx1 = fmaxf(mx1, __shfl_xor_sync(0xffffffffu, mx1, 1));
        mx1 = fmaxf(mx1, __shfl_xor_sync(0xffffffffu, mx1, 2));

        float mn0 = fmaxf(m0, mx0), mn1 = fmaxf(m1, mx1);
        float al0 = __expf(m0 - mn0), al1 = __expf(m1 - mn1);
        m0 = mn0; m1 = mn1;

        float rs0 = 0.f, rs1 = 0.f;
#pragma unroll
        for (int j = 0; j < 8; j++) {
            sacc[j][0] = __expf(sacc[j][0] - mn0); rs0 += sacc[j][0];
            sacc[j][1] = __expf(sacc[j][1] - mn0); rs0 += sacc[j][1];
            sacc[j][2] = __expf(sacc[j][2] - mn1); rs1 += sacc[j][2];
            sacc[j][3] = __expf(sacc[j][3] - mn1); rs1 += sacc[j][3];
        }
        rs0 += __shfl_xor_sync(0xffffffffu, rs0, 1);
        rs0 += __shfl_xor_sync(0xffffffffu, rs0, 2);
        rs1 += __shfl_xor_sync(0xffffffffu, rs1, 1);
        rs1 += __shfl_xor_sync(0xffffffffu, rs1, 2);
        l0s = l0s * al0 + rs0;
        l1s = l1s * al1 + rs1;

#pragma unroll
        for (int j = 0; j < 8; j++) {
            oacc[j][0] *= al0; oacc[j][1] *= al0;
            oacc[j][2] *= al1; oacc[j][3] *= al1;
        }

        // ---- O += P V, 3-term; P from registers, V frags from smem ----
#pragma unroll
        for (int cc = 0; cc < 4; cc++) {
            uint32_t ph[4], pl[4];
            split2(sacc[2 * cc][0],     sacc[2 * cc][1],     ph[0], pl[0]);
            split2(sacc[2 * cc][2],     sacc[2 * cc][3],     ph[1], pl[1]);
            split2(sacc[2 * cc + 1][0], sacc[2 * cc + 1][1], ph[2], pl[2]);
            split2(sacc[2 * cc + 1][2], sacc[2 * cc + 1][3], ph[3], pl[3]);
#pragma unroll
            for (int j2 = 0; j2 < 8; j2++) {
                int vo = (j2 * 8 + g) * 36 + cc * 8 + tg;
                uint32_t vh2[2] = { Vh[vo], Vh[vo + 4] };
                uint32_t vl2[2] = { Vl[vo], Vl[vo + 4] };
                mma_bf16(oacc[j2], ph, vh2);
                mma_bf16(oacc[j2], pl, vh2);
                mma_bf16(oacc[j2], ph, vl2);
            }
        }
    }

    // ---- finalize: write hi/lo bf16x2 directly for GEMM2 ----
    const float inv0 = 1.0f / l0s, inv1 = 1.0f / l1s;
    const size_t row0 = (size_t)(b * SEQ + qb * 64 + rb + g);
#pragma unroll
    for (int j2 = 0; j2 < 8; j2++) {
        uint32_t h0, l0, h1, l1;
        split2(oacc[j2][0] * inv0, oacc[j2][1] * inv0, h0, l0);
        split2(oacc[j2][2] * inv1, oacc[j2][3] * inv1, h1, l1);
        size_t idx0 = row0 * KH + h * 32 + j2 * 4 + tg;
        g_ah[idx0]            = h0;
        g_al[idx0]            = l0;
        g_ah[idx0 + 8 * KH]   = h1;
        g_al[idx0 + 8 * KH]   = l1;
    }
}

// ---------------------------------------------------------------------------
// launch
// ---------------------------------------------------------------------------
extern "C" void kernel_launch(void* const* d_in, const int* in_sizes, int n_in,
                              void* d_out, int out_size) {
    const float* x    = (const float*)d_in[0];   // [4,2048,1024]
    const float* Wqkv = (const float*)d_in[1];   // [3072,1024]
    const float* Wout = (const float*)d_in[2];   // [1024,1024]
    float*       out  = (float*)d_out;           // [4,2048,1024]

    float* qkv = nullptr;
    uint32_t *xh, *xl, *wqh, *wql, *woh, *wol, *ah, *al;
    cudaGetSymbolAddress((void**)&qkv, g_qkv);
    cudaGetSymbolAddress((void**)&xh,  g_xh);
    cudaGetSymbolAddress((void**)&xl,  g_xl);
    cudaGetSymbolAddress((void**)&wqh, g_wqh);
    cudaGetSymbolAddress((void**)&wql, g_wql);
    cudaGetSymbolAddress((void**)&woh, g_woh);
    cudaGetSymbolAddress((void**)&wol, g_wol);
    cudaGetSymbolAddress((void**)&ah,  g_ah);
    cudaGetSymbolAddress((void**)&al,  g_al);

    cudaFuncSetAttribute(attn_mma, cudaFuncAttributeMaxDynamicSharedMemorySize, AT_SMEM);

    // 0) split inputs
    const int n2x = ROWS * KH;
    const int n2q = QKVD * KH;
    const int n2o = DIMX * KH;
    cvt_split<<<n2x / 256, 256>>>(x,    xh,  xl,  n2x);
    cvt_split<<<n2q / 256, 256>>>(Wqkv, wqh, wql, n2q);
    cvt_split<<<n2o / 256, 256>>>(Wout, woh, wol, n2o);

    // 1) qkv = x @ Wqkv^T   [8192,3072] fp32
    dim3 g1(QKVD / 128, ROWS / 128);
    gemm_bf3<<<g1, 256>>>(xh, xl, wqh, wql, qkv, ROWS, QKVD, DIMX);

    // 1b) split qkv (Q pre-scaled) + build transposed V hi/lo
    cvt_qkv<<<(ROWS * KQ) / 256, 256>>>();
    dim3 gv(SEQ / 32, BATCH * NH);
    cvt_vT<<<gv, 256>>>();

    // 2) causal attention -> g_ah/g_al (bf16x2 hi/lo)
    dim3 g2(SEQ / 64, NH, BATCH);
    attn_mma<<<g2, 128, AT_SMEM>>>();

    // 3) out = att @ Wout^T [8192,1024]
    dim3 g3(DIMX / 128, ROWS / 128);
    gemm_bf3<<<g3, 256>>>(ah, al, woh, wol, out, ROWS, DIMX, DIMX);
}

// round 14
// speedup vs baseline: 2.6448x; 1.1078x over previous
#include <cuda_runtime.h>
#include <cstdint>

// ---------------------------------------------------------------------------
// Problem constants
// ---------------------------------------------------------------------------
#define DIMX   1024
#define NH     16
#define HD     64
#define BATCH  4
#define SEQ    2048
#define ROWS   (BATCH * SEQ)        // 8192
#define QKVD   (3 * DIMX)           // 3072
#define KH     (DIMX / 2)           // 512 u32 pairs per 1024 cols
#define KQ     (QKVD / 2)           // 1536 u32 pairs per qkv row

// ---------------------------------------------------------------------------
// Scratch (__device__ globals; allocation is forbidden)
// ---------------------------------------------------------------------------
__device__ float    g_qkv [(size_t)ROWS * QKVD];   // fp32 qkv (V section only is written)
__device__ uint32_t g_qkvh[(size_t)ROWS * KQ];     // qkv hi (Q pre-scaled)
__device__ uint32_t g_qkvl[(size_t)ROWS * KQ];     // qkv lo
__device__ uint32_t g_vth [(size_t)BATCH * NH * HD * (SEQ / 2)];  // V^T hi
__device__ uint32_t g_vtl [(size_t)BATCH * NH * HD * (SEQ / 2)];  // V^T lo
__device__ uint32_t g_xh  [(size_t)ROWS * KH];
__device__ uint32_t g_xl  [(size_t)ROWS * KH];
__device__ uint32_t g_wqh [(size_t)QKVD * KH];
__device__ uint32_t g_wql [(size_t)QKVD * KH];
__device__ uint32_t g_woh [(size_t)DIMX * KH];
__device__ uint32_t g_wol [(size_t)DIMX * KH];
__device__ uint32_t g_ah  [(size_t)ROWS * KH];     // attention out hi
__device__ uint32_t g_al  [(size_t)ROWS * KH];     // attention out lo

// ---------------------------------------------------------------------------
// helpers
// ---------------------------------------------------------------------------
__device__ __forceinline__ uint32_t smem_u32(const void* p) {
    uint32_t a;
    asm("{ .reg .u64 t; cvta.to.shared.u64 t, %1; cvt.u32.u64 %0, t; }"
        : "=r"(a) : "l"(p));
    return a;
}

__device__ __forceinline__ void split2(float x, float y, uint32_t& h, uint32_t& l) {
    asm("cvt.rn.bf16x2.f32 %0, %1, %2;" : "=r"(h) : "f"(y), "f"(x));
    float hx = __uint_as_float(h << 16);
    float hy = __uint_as_float(h & 0xFFFF0000u);
    asm("cvt.rn.bf16x2.f32 %0, %1, %2;" : "=r"(l) : "f"(y - hy), "f"(x - hx));
}

__global__ __launch_bounds__(256)
void cvt_split(const float* __restrict__ src,
               uint32_t* __restrict__ hi, uint32_t* __restrict__ lo, int n2) {
    int i = blockIdx.x * blockDim.x + threadIdx.x;
    if (i >= n2) return;
    float2 v = ((const float2*)src)[i];
    uint32_t h, l;
    split2(v.x, v.y, h, l);
    hi[i] = h;
    lo[i] = l;
}

// V^T split: out [b*NH+h][d][SEQ/2 pairs], pairs packed along key (token)
__global__ __launch_bounds__(256)
void cvt_vT() {
    __shared__ float tile[32][65];
    const int bh = blockIdx.y;
    const int b  = bh >> 4, h = bh & 15;
    const int t0 = blockIdx.x * 32;
    const int tid = threadIdx.x;
#pragma unroll
    for (int r = 0; r < 8; r++) {
        int e  = r * 256 + tid;
        int ti = e >> 6, d = e & 63;
        tile[ti][d] = g_qkv[(size_t)(b * SEQ + t0 + ti) * QKVD + 2 * DIMX + h * HD + d];
    }
    __syncthreads();
    const int d  = tid >> 2;
    const int pg = (tid & 3) * 4;
    size_t obase = ((size_t)bh * HD + d) * (SEQ / 2) + (t0 >> 1) + pg;
#pragma unroll
    for (int p = 0; p < 4; p++) {
        uint32_t hh, ll;
        split2(tile[2 * (pg + p)][d], tile[2 * (pg + p) + 1][d], hh, ll);
        g_vth[obase + p] = hh;
        g_vtl[obase + p] = ll;
    }
}

// mma.sync m16n8k16 bf16 (row.col), fp32 accumulate
__device__ __forceinline__ void mma_bf16(float* d, const uint32_t* a, const uint32_t* b) {
    asm volatile(
        "mma.sync.aligned.m16n8k16.row.col.f32.bf16.bf16.f32 "
        "{%0,%1,%2,%3}, {%4,%5,%6,%7}, {%8,%9}, {%0,%1,%2,%3};"
        : "+f"(d[0]), "+f"(d[1]), "+f"(d[2]), "+f"(d[3])
        : "r"(a[0]), "r"(a[1]), "r"(a[2]), "r"(a[3]), "r"(b[0]), "r"(b[1]));
}

__device__ __forceinline__ void ldsm4(uint32_t* r, uint32_t addr) {
    asm volatile("ldmatrix.sync.aligned.m8n8.x4.shared.b16 {%0,%1,%2,%3}, [%4];"
                 : "=r"(r[0]), "=r"(r[1]), "=r"(r[2]), "=r"(r[3]) : "r"(addr));
}

// ---------------------------------------------------------------------------
// 3-term bf16 NT GEMM with ldmatrix fragment loads.
// C[M,N] = A[M,K] * B[N,K]^T. CTA 128x128, 256 thr (8 warps 2x4), warp 64x32.
// Tile layout: [128 rows][8 u32], 16B chunk swizzle c' = c ^ ((row>>2)&1).
//   - staging st.v4: each 8-lane phase hits 8 distinct 16B bank groups.
//   - ldmatrix: 8 rows x fixed chunk -> 8 distinct groups (conflict-free).
// MODE 0: write fp32 C.  MODE 1 (qkv): write g_qkvh/l split (Q scaled 0.125)
// and fp32 g_qkv for the V third only.
// ---------------------------------------------------------------------------
#define P_AH 0
#define P_AL 1024
#define P_BH 2048
#define P_BL 3072
#define BUFSZ 4096

template<int MODE>
__global__ __launch_bounds__(256, 2)
void gemm_bf3(const uint32_t* __restrict__ Ah_, const uint32_t* __restrict__ Al_,
              const uint32_t* __restrict__ Bh_, const uint32_t* __restrict__ Bl_,
              float* __restrict__ C, int M, int N, int K) {
    __shared__ uint32_t smbuf[2 * BUFSZ];   // 32 KB

    const int tid   = threadIdx.x;
    const int lane  = tid & 31;
    const int wid   = tid >> 5;
    const int warpm = wid >> 2;
    const int warpn = wid & 3;
    const int g     = lane >> 2;
    const int tg    = lane & 3;
    const int bm    = blockIdx.y << 7;
    const int bn    = blockIdx.x << 7;
    const int KP    = K >> 1;

    // staging: thread = (row, 16B half); swizzled 16B chunk
    const int srow  = tid >> 1;
    const int shalf = tid & 1;
    const uint32_t stIdx = (uint32_t)srow * 8 + 4 * (shalf ^ ((srow >> 2) & 1));

    // ldmatrix lane addresses (u32 index within a tile)
    const int rA = warpm * 64 + (lane & 15);
    const int cA = lane >> 4;
    const uint32_t offA = (uint32_t)rA * 8 + 4 * (cA ^ ((rA >> 2) & 1));
    const int rB = warpn * 32 + (lane & 7) + ((lane >> 4) << 3);
    const int cB = (lane >> 3) & 1;
    const uint32_t offB = (uint32_t)rB * 8 + 4 * (cB ^ ((rB >> 2) & 1));

    const uint32_t sb = smem_u32(smbuf);

    const uint32_t* pAh = Ah_ + (size_t)(bm + srow) * KP + shalf * 4;
    const uint32_t* pAl = Al_ + (size_t)(bm + srow) * KP + shalf * 4;
    const uint32_t* pBh = Bh_ + (size_t)(bn + srow) * KP + shalf * 4;
    const uint32_t* pBl = Bl_ + (size_t)(bn + srow) * KP + shalf * 4;

    float acc[4][4][4];
#pragma unroll
    for (int i = 0; i < 4; i++)
#pragma unroll
        for (int j = 0; j < 4; j++)
#pragma unroll
            for (int q = 0; q < 4; q++) acc[i][j][q] = 0.f;

    const int nt = K >> 4;

    uint4 vah = *(const uint4*)(pAh);
    uint4 val = *(const uint4*)(pAl);
    uint4 vbh = *(const uint4*)(pBh);
    uint4 vbl = *(const uint4*)(pBl);
    *(uint4*)(smbuf + P_AH + stIdx) = vah;
    *(uint4*)(smbuf + P_AL + stIdx) = val;
    *(uint4*)(smbuf + P_BH + stIdx) = vbh;
    *(uint4*)(smbuf + P_BL + stIdx) = vbl;
    __syncthreads();

    for (int t = 0; t < nt; t++) {
        const uint32_t base = sb + ((t & 1) ? BUFSZ * 4 : 0);

        if (t + 1 < nt) {
            vah = *(const uint4*)(pAh + (t + 1) * 8);
            val = *(const uint4*)(pAl + (t + 1) * 8);
            vbh = *(const uint4*)(pBh + (t + 1) * 8);
            vbl = *(const uint4*)(pBl + (t + 1) * 8);
        }

        // B fragments: bh0 = {b0[0],b0[1],b1[0],b1[1]}, bh1 -> j=2,3
        uint32_t bh0[4], bh1[4], bl0[4], bl1[4];
        ldsm4(bh0, base + (P_BH + offB) * 4);
        ldsm4(bh1, base + (P_BH + offB) * 4 + 512);
        ldsm4(bl0, base + (P_BL + offB) * 4);
        ldsm4(bl1, base + (P_BL + offB) * 4 + 512);

#pragma unroll
        for (int i = 0; i < 4; i++) {
            uint32_t ah[4], al[4];
            ldsm4(ah, base + (P_AH + offA) * 4 + i * 512);
            ldsm4(al, base + (P_AL + offA) * 4 + i * 512);
            // t1: Ah*Bh
            mma_bf16(acc[i][0], ah, &bh0[0]);
            mma_bf16(acc[i][1], ah, &bh0[2]);
            mma_bf16(acc[i][2], ah, &bh1[0]);
            mma_bf16(acc[i][3], ah, &bh1[2]);
            // t3: Ah*Bl
            mma_bf16(acc[i][0], ah, &bl0[0]);
            mma_bf16(acc[i][1], ah, &bl0[2]);
            mma_bf16(acc[i][2], ah, &bl1[0]);
            mma_bf16(acc[i][3], ah, &bl1[2]);
            // t2: Al*Bh
            mma_bf16(acc[i][0], al, &bh0[0]);
            mma_bf16(acc[i][1], al, &bh0[2]);
            mma_bf16(acc[i][2], al, &bh1[0]);
            mma_bf16(acc[i][3], al, &bh1[2]);
        }

        if (t + 1 < nt) {
            uint32_t* D = smbuf + ((t + 1) & 1) * BUFSZ;
            *(uint4*)(D + P_AH + stIdx) = vah;
            *(uint4*)(D + P_AL + stIdx) = val;
            *(uint4*)(D + P_BH + stIdx) = vbh;
            *(uint4*)(D + P_BL + stIdx) = vbl;
        }
        __syncthreads();
    }

    if (MODE == 0) {
#pragma unroll
        for (int i = 0; i < 4; i++) {
            int row = bm + warpm * 64 + i * 16 + g;
#pragma unroll
            for (int j = 0; j < 4; j++) {
                int col = bn + warpn * 32 + j * 8 + 2 * tg;
                *(float2*)&C[(size_t)row * N + col]       = make_float2(acc[i][j][0], acc[i][j][1]);
                *(float2*)&C[(size_t)(row + 8) * N + col] = make_float2(acc[i][j][2], acc[i][j][3]);
            }
        }
    } else {
        const float sc = (bn < 1024) ? 0.125f : 1.0f;   // Q pre-scale (exact, pow2)
        const bool  wv = (bn >= 2048);                  // V third -> fp32 for cvt_vT
#pragma unroll
        for (int i = 0; i < 4; i++) {
            int row = bm + warpm * 64 + i * 16 + g;
#pragma unroll
            for (int j = 0; j < 4; j++) {
                int col  = bn + warpn * 32 + j * 8 + 2 * tg;
                int colp = col >> 1;
                uint32_t h0, l0, h1, l1;
                split2(acc[i][j][0] * sc, acc[i][j][1] * sc, h0, l0);
                split2(acc[i][j][2] * sc, acc[i][j][3] * sc, h1, l1);
                g_qkvh[(size_t)row * KQ + colp]       = h0;
                g_qkvl[(size_t)row * KQ + colp]       = l0;
                g_qkvh[(size_t)(row + 8) * KQ + colp] = h1;
                g_qkvl[(size_t)(row + 8) * KQ + colp] = l1;
                if (wv) {
                    *(float2*)&g_qkv[(size_t)row * QKVD + col]       = make_float2(acc[i][j][0], acc[i][j][1]);
                    *(float2*)&g_qkv[(size_t)(row + 8) * QKVD + col] = make_float2(acc[i][j][2], acc[i][j][3]);
                }
            }
        }
    }
}

// ---------------------------------------------------------------------------
// Causal flash attention, mma.sync, all operands pre-split in gmem.
// (unchanged from R13 — proven at ~500us)
// ---------------------------------------------------------------------------
#define AT_SMEM (12800 * 4)

__global__ __launch_bounds__(128, 3)
void attn_mma() {
    extern __shared__ uint32_t sm[];
    uint32_t* Qh = sm;
    uint32_t* Ql = sm + 2048;
    uint32_t* Kh = sm + 4096;
    uint32_t* Kl = sm + 6144;
    uint32_t* Vh = sm + 8192;
    uint32_t* Vl = sm + 10496;

    const int tid  = threadIdx.x;
    const int lane = tid & 31;
    const int wid  = tid >> 5;
    const int g    = lane >> 2;
    const int tg   = lane & 3;
    const int rb   = wid << 4;
    const int qb   = blockIdx.x;
    const int h    = blockIdx.y;
    const int b    = blockIdx.z;

    const int srow = tid >> 1;
    const int shf  = tid & 1;
    const int s    = srow & 7;

    // ---- stage Q (pre-scaled hi/lo from gmem) ----
    {
        size_t base = (size_t)(b * SEQ + qb * 64 + srow) * KQ + h * 32 + shf * 16;
#pragma unroll
        for (int i = 0; i < 4; i++) {
            uint4 vh4 = *(const uint4*)(g_qkvh + base + i * 4);
            uint4 vl4 = *(const uint4*)(g_qkvl + base + i * 4);
            int p0 = shf * 16 + i * 4;
            int sbase = ((p0 >> 3) * 64 + srow) * 8;
            int kp = p0 & 7;
            Qh[sbase + ((kp + 0) ^ s)] = vh4.x;
            Qh[sbase + ((kp + 1) ^ s)] = vh4.y;
            Qh[sbase + ((kp + 2) ^ s)] = vh4.z;
            Qh[sbase + ((kp + 3) ^ s)] = vh4.w;
            Ql[sbase + ((kp + 0) ^ s)] = vl4.x;
            Ql[sbase + ((kp + 1) ^ s)] = vl4.y;
            Ql[sbase + ((kp + 2) ^ s)] = vl4.z;
            Ql[sbase + ((kp + 3) ^ s)] = vl4.w;
        }
    }

    float m0 = -1e30f, m1 = -1e30f, l0s = 0.f, l1s = 0.f;
    float oacc[8][4];
#pragma unroll
    for (int j = 0; j < 8; j++)
#pragma unroll
        for (int q = 0; q < 4; q++) oacc[j][q] = 0.f;

    const int c0 = tg ^ g;
    const int c1 = (tg + 4) ^ g;

    for (int kb = 0; kb <= qb; kb++) {
        __syncthreads();

        // ---- stage K hi/lo ----
        {
            size_t base = (size_t)(b * SEQ + kb * 64 + srow) * KQ + 512 + h * 32 + shf * 16;
#pragma unroll
            for (int i = 0; i < 4; i++) {
                uint4 vh4 = *(const uint4*)(g_qkvh + base + i * 4);
                uint4 vl4 = *(const uint4*)(g_qkvl + base + i * 4);
                int p0 = shf * 16 + i * 4;
                int sbase = ((p0 >> 3) * 64 + srow) * 8;
                int kp = p0 & 7;
                Kh[sbase + ((kp + 0) ^ s)] = vh4.x;
                Kh[sbase + ((kp + 1) ^ s)] = vh4.y;
                Kh[sbase + ((kp + 2) ^ s)] = vh4.z;
                Kh[sbase + ((kp + 3) ^ s)] = vh4.w;
                Kl[sbase + ((kp + 0) ^ s)] = vl4.x;
                Kl[sbase + ((kp + 1) ^ s)] = vl4.y;
                Kl[sbase + ((kp + 2) ^ s)] = vl4.z;
                Kl[sbase + ((kp + 3) ^ s)] = vl4.w;
            }
        }
        // ---- stage V^T hi/lo (pairs along key) ----
        {
            size_t vbase = ((size_t)(b * NH + h) * HD + srow) * (SEQ / 2) + kb * 32 + shf * 16;
            int d36 = srow * 36 + shf * 16;
#pragma unroll
            for (int i = 0; i < 4; i++) {
                *(uint4*)(Vh + d36 + i * 4) = *(const uint4*)(g_vth + vbase + i * 4);
                *(uint4*)(Vl + d36 + i * 4) = *(const uint4*)(g_vtl + vbase + i * 4);
            }
        }
        __syncthreads();

        // ---- S = Q K^T, 3-term ----
        float sacc[8][4];
#pragma unroll
        for (int j = 0; j < 8; j++)
#pragma unroll
            for (int q = 0; q < 4; q++) sacc[j][q] = 0.f;

#pragma unroll
        for (int c = 0; c < 4; c++) {
            uint32_t a[4], bb[8][2];
            const int ab  = c * 512 + (rb + g) * 8;
            const int ab8 = c * 512 + (rb + g + 8) * 8;
            a[0] = Qh[ab + c0];  a[1] = Qh[ab8 + c0];
            a[2] = Qh[ab + c1];  a[3] = Qh[ab8 + c1];
#pragma unroll
            for (int j = 0; j < 8; j++) {
                int nb = c * 512 + (j * 8 + g) * 8;
                bb[j][0] = Kh[nb + c0];
                bb[j][1] = Kh[nb + c1];
            }
#pragma unroll
            for (int j = 0; j < 8; j++) mma_bf16(sacc[j], a, bb[j]);
#pragma unroll
            for (int j = 0; j < 8; j++) {
                int nb = c * 512 + (j * 8 + g) * 8;
                bb[j][0] = Kl[nb + c0];
                bb[j][1] = Kl[nb + c1];
            }
#pragma unroll
            for (int j = 0; j < 8; j++) mma_bf16(sacc[j], a, bb[j]);
            a[0] = Ql[ab + c0];  a[1] = Ql[ab8 + c0];
            a[2] = Ql[ab + c1];  a[3] = Ql[ab8 + c1];
#pragma unroll
            for (int j = 0; j < 8; j++) {
                int nb = c * 512 + (j * 8 + g) * 8;
                bb[j][0] = Kh[nb + c0];
                bb[j][1] = Kh[nb + c1];
            }
#pragma unroll
            for (int j = 0; j < 8; j++) mma_bf16(sacc[j], a, bb[j]);
        }

        // ---- causal mask on diagonal block ----
        if (kb == qb) {
            const int r0 = rb + g, r1 = rb + g + 8;
#pragma unroll
            for (int j = 0; j < 8; j++) {
                int col = j * 8 + 2 * tg;
                if (col     > r0) sacc[j][0] = -1e30f;
                if (col + 1 > r0) sacc[j][1] = -1e30f;
                if (col     > r1) sacc[j][2] = -1e30f;
                if (col + 1 > r1) sacc[j][3] = -1e30f;
            }
        }

        // ---- online softmax ----
        float mx0 = -1e30f, mx1 = -1e30f;
#pragma unroll
        for (int j = 0; j < 8; j++) {
            mx0 = fmaxf(mx0, fmaxf(sacc[j][0], sacc[j][1]));
            mx1 = fmaxf(mx1, fmaxf(sacc[j][2], sacc[j][3]));
        }
        mx0 = fmaxf(mx0, __shfl_xor_sync(0xffffffffu, mx0, 1));
        mx0 = fmaxf(mx0, __shfl_xor_sync(0xffffffffu, mx0, 2));
        mx1 = fmaxf(mx1, __shfl_xor_sync(0xffffffffu, mx1, 1));
        mx1 = fmaxf(mx1, __shfl_xor_sync(0xffffffffu, mx1, 2));

        float mn0 = fmaxf(m0, mx0), mn1 = fmaxf(m1, mx1);
        float al0 = __expf(m0 - mn0), al1 = __expf(m1 - mn1);
        m0 = mn0; m1 = mn1;

        float rs0 = 0.f, rs1 = 0.f;
#pragma unroll
        for (int j = 0; j < 8; j++) {
            sacc[j][0] = __expf(sacc[j][0] - mn0); rs0 += sacc[j][0];
            sacc[j][1] = __expf(sacc[j][1] - mn0); rs0 += sacc[j][1];
            sacc[j][2] = __expf(sacc[j][2] - mn1); rs1 += sacc[j][2];
            sacc[j][3] = __expf(sacc[j][3] - mn1); rs1 += sacc[j][3];
        }
        rs0 += __shfl_xor_sync(0xffffffffu, rs0, 1);
        rs0 += __shfl_xor_sync(0xffffffffu, rs0, 2);
        rs1 += __shfl_xor_sync(0xffffffffu, rs1, 1);
        rs1 += __shfl_xor_sync(0xffffffffu, rs1, 2);
        l0s = l0s * al0 + rs0;
        l1s = l1s * al1 + rs1;

#pragma unroll
        for (int j = 0; j < 8; j++) {
            oacc[j][0] *= al0; oacc[j][1] *= al0;
            oacc[j][2] *= al1; oacc[j][3] *= al1;
        }

        // ---- O += P V, 3-term ----
#pragma unroll
        for (int cc = 0; cc < 4; cc++) {
            uint32_t ph[4], pl[4];
            split2(sacc[2 * cc][0],     sacc[2 * cc][1],     ph[0], pl[0]);
            split2(sacc[2 * cc][2],     sacc[2 * cc][3],     ph[1], pl[1]);
            split2(sacc[2 * cc + 1][0], sacc[2 * cc + 1][1], ph[2], pl[2]);
            split2(sacc[2 * cc + 1][2], sacc[2 * cc + 1][3], ph[3], pl[3]);
#pragma unroll
            for (int j2 = 0; j2 < 8; j2++) {
                int vo = (j2 * 8 + g) * 36 + cc * 8 + tg;
                uint32_t vh2[2] = { Vh[vo], Vh[vo + 4] };
                uint32_t vl2[2] = { Vl[vo], Vl[vo + 4] };
                mma_bf16(oacc[j2], ph, vh2);
                mma_bf16(oacc[j2], pl, vh2);
                mma_bf16(oacc[j2], ph, vl2);
            }
        }
    }

    // ---- finalize: write hi/lo bf16x2 directly for GEMM2 ----
    const float inv0 = 1.0f / l0s, inv1 = 1.0f / l1s;
    const size_t row0 = (size_t)(b * SEQ + qb * 64 + rb + g);
#pragma unroll
    for (int j2 = 0; j2 < 8; j2++) {
        uint32_t h0, l0, h1, l1;
        split2(oacc[j2][0] * inv0, oacc[j2][1] * inv0, h0, l0);
        split2(oacc[j2][2] * inv1, oacc[j2][3] * inv1, h1, l1);
        size_t idx0 = row0 * KH + h * 32 + j2 * 4 + tg;
        g_ah[idx0]            = h0;
        g_al[idx0]            = l0;
        g_ah[idx0 + 8 * KH]   = h1;
        g_al[idx0 + 8 * KH]   = l1;
    }
}

// ---------------------------------------------------------------------------
// launch
// ---------------------------------------------------------------------------
extern "C" void kernel_launch(void* const* d_in, const int* in_sizes, int n_in,
                              void* d_out, int out_size) {
    const float* x    = (const float*)d_in[0];   // [4,2048,1024]
    const float* Wqkv = (const float*)d_in[1];   // [3072,1024]
    const float* Wout = (const float*)d_in[2];   // [1024,1024]
    float*       out  = (float*)d_out;           // [4,2048,1024]

    uint32_t *xh, *xl, *wqh, *wql, *woh, *wol, *ah, *al;
    cudaGetSymbolAddress((void**)&xh,  g_xh);
    cudaGetSymbolAddress((void**)&xl,  g_xl);
    cudaGetSymbolAddress((void**)&wqh, g_wqh);
    cudaGetSymbolAddress((void**)&wql, g_wql);
    cudaGetSymbolAddress((void**)&woh, g_woh);
    cudaGetSymbolAddress((void**)&wol, g_wol);
    cudaGetSymbolAddress((void**)&ah,  g_ah);
    cudaGetSymbolAddress((void**)&al,  g_al);

    cudaFuncSetAttribute(attn_mma, cudaFuncAttributeMaxDynamicSharedMemorySize, AT_SMEM);

    // 0) split inputs
    const int n2x = ROWS * KH;
    const int n2q = QKVD * KH;
    const int n2o = DIMX * KH;
    cvt_split<<<n2x / 256, 256>>>(x,    xh,  xl,  n2x);
    cvt_split<<<n2q / 256, 256>>>(Wqkv, wqh, wql, n2q);
    cvt_split<<<n2o / 256, 256>>>(Wout, woh, wol, n2o);

    // 1) qkv = x @ Wqkv^T — fused epilogue writes split hi/lo (+ fp32 V third)
    dim3 g1(QKVD / 128, ROWS / 128);
    gemm_bf3<1><<<g1, 256>>>(xh, xl, wqh, wql, nullptr, ROWS, QKVD, DIMX);

    // 1b) build transposed V hi/lo
    dim3 gv(SEQ / 32, BATCH * NH);
    cvt_vT<<<gv, 256>>>();

    // 2) causal attention -> g_ah/g_al (bf16x2 hi/lo)
    dim3 g2(SEQ / 64, NH, BATCH);
    attn_mma<<<g2, 128, AT_SMEM>>>();

    // 3) out = att @ Wout^T [8192,1024]
    dim3 g3(DIMX / 128, ROWS / 128);
    gemm_bf3<0><<<g3, 256>>>(ah, al, woh, wol, out, ROWS, DIMX, DIMX);
}

// round 15
// speedup vs baseline: 2.7533x; 1.0410x over previous
#include <cuda_runtime.h>
#include <cstdint>

// ---------------------------------------------------------------------------
// Problem constants
// ---------------------------------------------------------------------------
#define DIMX   1024
#define NH     16
#define HD     64
#define BATCH  4
#define SEQ    2048
#define ROWS   (BATCH * SEQ)        // 8192
#define QKVD   (3 * DIMX)           // 3072
#define KH     (DIMX / 2)           // 512 u32 pairs per 1024 cols
#define KQ     (QKVD / 2)           // 1536 u32 pairs per qkv row

// ---------------------------------------------------------------------------
// Scratch (__device__ globals; allocation is forbidden)
// ---------------------------------------------------------------------------
__device__ float    g_qkv [(size_t)ROWS * QKVD];   // fp32 qkv (V section only)
__device__ uint32_t g_qkvh[(size_t)ROWS * KQ];     // qkv hi (Q pre-scaled)
__device__ uint32_t g_qkvl[(size_t)ROWS * KQ];     // qkv lo
__device__ uint32_t g_vth [(size_t)BATCH * NH * HD * (SEQ / 2)];  // V^T hi
__device__ uint32_t g_vtl [(size_t)BATCH * NH * HD * (SEQ / 2)];  // V^T lo
__device__ uint32_t g_xh  [(size_t)ROWS * KH];
__device__ uint32_t g_xl  [(size_t)ROWS * KH];
__device__ uint32_t g_wqh [(size_t)QKVD * KH];
__device__ uint32_t g_wql [(size_t)QKVD * KH];
__device__ uint32_t g_woh [(size_t)DIMX * KH];
__device__ uint32_t g_wol [(size_t)DIMX * KH];
__device__ uint32_t g_ah  [(size_t)ROWS * KH];     // attention out hi
__device__ uint32_t g_al  [(size_t)ROWS * KH];     // attention out lo

// ---------------------------------------------------------------------------
// helpers
// ---------------------------------------------------------------------------
__device__ __forceinline__ uint32_t smem_u32(const void* p) {
    uint32_t a;
    asm("{ .reg .u64 t; cvta.to.shared.u64 t, %1; cvt.u32.u64 %0, t; }"
        : "=r"(a) : "l"(p));
    return a;
}

__device__ __forceinline__ void split2(float x, float y, uint32_t& h, uint32_t& l) {
    asm("cvt.rn.bf16x2.f32 %0, %1, %2;" : "=r"(h) : "f"(y), "f"(x));
    float hx = __uint_as_float(h << 16);
    float hy = __uint_as_float(h & 0xFFFF0000u);
    asm("cvt.rn.bf16x2.f32 %0, %1, %2;" : "=r"(l) : "f"(y - hy), "f"(x - hx));
}

__device__ __forceinline__ void cp16(uint32_t saddr, const void* gptr) {
    asm volatile("cp.async.cg.shared.global [%0], [%1], 16;"
                 :: "r"(saddr), "l"(gptr) : "memory");
}
#define CP_COMMIT() asm volatile("cp.async.commit_group;" ::: "memory")
template<int N>
__device__ __forceinline__ void cp_wait() {
    asm volatile("cp.async.wait_group %0;" :: "n"(N) : "memory");
}

__global__ __launch_bounds__(256)
void cvt_split(const float* __restrict__ src,
               uint32_t* __restrict__ hi, uint32_t* __restrict__ lo, int n2) {
    int i = blockIdx.x * blockDim.x + threadIdx.x;
    if (i >= n2) return;
    float2 v = ((const float2*)src)[i];
    uint32_t h, l;
    split2(v.x, v.y, h, l);
    hi[i] = h;
    lo[i] = l;
}

// V^T split: out [b*NH+h][d][SEQ/2 pairs], pairs packed along key (token)
__global__ __launch_bounds__(256)
void cvt_vT() {
    __shared__ float tile[32][65];
    const int bh = blockIdx.y;
    const int b  = bh >> 4, h = bh & 15;
    const int t0 = blockIdx.x * 32;
    const int tid = threadIdx.x;
#pragma unroll
    for (int r = 0; r < 8; r++) {
        int e  = r * 256 + tid;
        int ti = e >> 6, d = e & 63;
        tile[ti][d] = g_qkv[(size_t)(b * SEQ + t0 + ti) * QKVD + 2 * DIMX + h * HD + d];
    }
    __syncthreads();
    const int d  = tid >> 2;
    const int pg = (tid & 3) * 4;
    size_t obase = ((size_t)bh * HD + d) * (SEQ / 2) + (t0 >> 1) + pg;
#pragma unroll
    for (int p = 0; p < 4; p++) {
        uint32_t hh, ll;
        split2(tile[2 * (pg + p)][d], tile[2 * (pg + p) + 1][d], hh, ll);
        g_vth[obase + p] = hh;
        g_vtl[obase + p] = ll;
    }
}

// mma.sync m16n8k16 bf16 (row.col), fp32 accumulate
__device__ __forceinline__ void mma_bf16(float* d, const uint32_t* a, const uint32_t* b) {
    asm volatile(
        "mma.sync.aligned.m16n8k16.row.col.f32.bf16.bf16.f32 "
        "{%0,%1,%2,%3}, {%4,%5,%6,%7}, {%8,%9}, {%0,%1,%2,%3};"
        : "+f"(d[0]), "+f"(d[1]), "+f"(d[2]), "+f"(d[3])
        : "r"(a[0]), "r"(a[1]), "r"(a[2]), "r"(a[3]), "r"(b[0]), "r"(b[1]));
}

__device__ __forceinline__ void ldsm4(uint32_t* r, uint32_t addr) {
    asm volatile("ldmatrix.sync.aligned.m8n8.x4.shared.b16 {%0,%1,%2,%3}, [%4];"
                 : "=r"(r[0]), "=r"(r[1]), "=r"(r[2]), "=r"(r[3]) : "r"(addr));
}

// ---------------------------------------------------------------------------
// 3-term bf16 NT GEMM, ldmatrix + 3-stage cp.async pipeline.
// C[M,N] = A[M,K] * B[N,K]^T. CTA 128x128, 256 thr (8 warps 2x4), warp 64x32.
// Tile layout: [128 rows][8 u32], 16B chunk swizzle c' = c ^ ((row>>2)&1).
// MODE 0: fp32 C.  MODE 1: split epilogue for qkv (Q scaled; fp32 V third).
// ---------------------------------------------------------------------------
#define P_AH 0
#define P_AL 1024
#define P_BH 2048
#define P_BL 3072
#define BUFSZ 4096
#define NSTAGE 3

template<int MODE>
__global__ __launch_bounds__(256, 2)
void gemm_bf3(const uint32_t* __restrict__ Ah_, const uint32_t* __restrict__ Al_,
              const uint32_t* __restrict__ Bh_, const uint32_t* __restrict__ Bl_,
              float* __restrict__ C, int M, int N, int K) {
    __shared__ uint32_t smbuf[NSTAGE * BUFSZ];   // 48 KB

    const int tid   = threadIdx.x;
    const int lane  = tid & 31;
    const int wid   = tid >> 5;
    const int warpm = wid >> 2;
    const int warpn = wid & 3;
    const int g     = lane >> 2;
    const int tg    = lane & 3;
    const int bm    = blockIdx.y << 7;
    const int bn    = blockIdx.x << 7;
    const int KP    = K >> 1;

    // staging: thread = (row, 16B half); swizzled 16B chunk
    const int srow  = tid >> 1;
    const int shalf = tid & 1;
    const uint32_t stIdx = (uint32_t)srow * 8 + 4 * (shalf ^ ((srow >> 2) & 1));

    // ldmatrix lane addresses (u32 index within a tile)
    const int rA = warpm * 64 + (lane & 15);
    const int cA = lane >> 4;
    const uint32_t offA = (uint32_t)rA * 8 + 4 * (cA ^ ((rA >> 2) & 1));
    const int rB = warpn * 32 + (lane & 7) + ((lane >> 4) << 3);
    const int cB = (lane >> 3) & 1;
    const uint32_t offB = (uint32_t)rB * 8 + 4 * (cB ^ ((rB >> 2) & 1));

    const uint32_t sb = smem_u32(smbuf);

    const uint32_t* pAh = Ah_ + (size_t)(bm + srow) * KP + shalf * 4;
    const uint32_t* pAl = Al_ + (size_t)(bm + srow) * KP + shalf * 4;
    const uint32_t* pBh = Bh_ + (size_t)(bn + srow) * KP + shalf * 4;
    const uint32_t* pBl = Bl_ + (size_t)(bn + srow) * KP + shalf * 4;

    float acc[4][4][4];
#pragma unroll
    for (int i = 0; i < 4; i++)
#pragma unroll
        for (int j = 0; j < 4; j++)
#pragma unroll
            for (int q = 0; q < 4; q++) acc[i][j][q] = 0.f;

    const int nt = K >> 4;

    // prologue: issue chunks 0 and 1
#pragma unroll
    for (int p = 0; p < 2; p++) {
        uint32_t dstb = sb + p * (BUFSZ * 4);
        cp16(dstb + (P_AH + stIdx) * 4, pAh + p * 8);
        cp16(dstb + (P_AL + stIdx) * 4, pAl + p * 8);
        cp16(dstb + (P_BH + stIdx) * 4, pBh + p * 8);
        cp16(dstb + (P_BL + stIdx) * 4, pBl + p * 8);
        CP_COMMIT();
    }

    int stage = 0;
    for (int t = 0; t < nt; t++) {
        cp_wait<1>();          // chunk t landed
        __syncthreads();       // all warps done reading stage (t-1)%3 too

        if (t + 2 < nt) {      // issue chunk t+2 into the stage just freed
            uint32_t dstb = sb + ((stage + 2 >= NSTAGE) ? (stage + 2 - NSTAGE) : (stage + 2)) * (BUFSZ * 4);
            cp16(dstb + (P_AH + stIdx) * 4, pAh + (size_t)(t + 2) * 8);
            cp16(dstb + (P_AL + stIdx) * 4, pAl + (size_t)(t + 2) * 8);
            cp16(dstb + (P_BH + stIdx) * 4, pBh + (size_t)(t + 2) * 8);
            cp16(dstb + (P_BL + stIdx) * 4, pBl + (size_t)(t + 2) * 8);
            CP_COMMIT();
        }

        const uint32_t base = sb + stage * (BUFSZ * 4);

        uint32_t bh0[4], bh1[4], bl0[4], bl1[4];
        ldsm4(bh0, base + (P_BH + offB) * 4);
        ldsm4(bh1, base + (P_BH + offB) * 4 + 512);
        ldsm4(bl0, base + (P_BL + offB) * 4);
        ldsm4(bl1, base + (P_BL + offB) * 4 + 512);

#pragma unroll
        for (int i = 0; i < 4; i++) {
            uint32_t ah[4], al[4];
            ldsm4(ah, base + (P_AH + offA) * 4 + i * 512);
            ldsm4(al, base + (P_AL + offA) * 4 + i * 512);
            mma_bf16(acc[i][0], ah, &bh0[0]);
            mma_bf16(acc[i][1], ah, &bh0[2]);
            mma_bf16(acc[i][2], ah, &bh1[0]);
            mma_bf16(acc[i][3], ah, &bh1[2]);
            mma_bf16(acc[i][0], ah, &bl0[0]);
            mma_bf16(acc[i][1], ah, &bl0[2]);
            mma_bf16(acc[i][2], ah, &bl1[0]);
            mma_bf16(acc[i][3], ah, &bl1[2]);
            mma_bf16(acc[i][0], al, &bh0[0]);
            mma_bf16(acc[i][1], al, &bh0[2]);
            mma_bf16(acc[i][2], al, &bh1[0]);
            mma_bf16(acc[i][3], al, &bh1[2]);
        }

        stage = (stage + 1 == NSTAGE) ? 0 : stage + 1;
    }

    if (MODE == 0) {
#pragma unroll
        for (int i = 0; i < 4; i++) {
            int row = bm + warpm * 64 + i * 16 + g;
#pragma unroll
            for (int j = 0; j < 4; j++) {
                int col = bn + warpn * 32 + j * 8 + 2 * tg;
                *(float2*)&C[(size_t)row * N + col]       = make_float2(acc[i][j][0], acc[i][j][1]);
                *(float2*)&C[(size_t)(row + 8) * N + col] = make_float2(acc[i][j][2], acc[i][j][3]);
            }
        }
    } else {
        const float sc = (bn < 1024) ? 0.125f : 1.0f;   // Q pre-scale (exact, pow2)
        const bool  wv = (bn >= 2048);                  // V third -> fp32 for cvt_vT
#pragma unroll
        for (int i = 0; i < 4; i++) {
            int row = bm + warpm * 64 + i * 16 + g;
#pragma unroll
            for (int j = 0; j < 4; j++) {
                int col  = bn + warpn * 32 + j * 8 + 2 * tg;
                int colp = col >> 1;
                uint32_t h0, l0, h1, l1;
                split2(acc[i][j][0] * sc, acc[i][j][1] * sc, h0, l0);
                split2(acc[i][j][2] * sc, acc[i][j][3] * sc, h1, l1);
                g_qkvh[(size_t)row * KQ + colp]       = h0;
                g_qkvl[(size_t)row * KQ + colp]       = l0;
                g_qkvh[(size_t)(row + 8) * KQ + colp] = h1;
                g_qkvl[(size_t)(row + 8) * KQ + colp] = l1;
                if (wv) {
                    *(float2*)&g_qkv[(size_t)row * QKVD + col]       = make_float2(acc[i][j][0], acc[i][j][1]);
                    *(float2*)&g_qkv[(size_t)(row + 8) * QKVD + col] = make_float2(acc[i][j][2], acc[i][j][3]);
                }
            }
        }
    }
}

// ---------------------------------------------------------------------------
// Causal flash attention, mma.sync, operands pre-split in gmem.
// V^T staging moved to cp.async (overlaps with scalar K staging).
// ---------------------------------------------------------------------------
#define AT_SMEM (12800 * 4)

__global__ __launch_bounds__(128, 3)
void attn_mma() {
    extern __shared__ uint32_t sm[];
    uint32_t* Qh = sm;
    uint32_t* Ql = sm + 2048;
    uint32_t* Kh = sm + 4096;
    uint32_t* Kl = sm + 6144;
    uint32_t* Vh = sm + 8192;
    uint32_t* Vl = sm + 10496;

    const int tid  = threadIdx.x;
    const int lane = tid & 31;
    const int wid  = tid >> 5;
    const int g    = lane >> 2;
    const int tg   = lane & 3;
    const int rb   = wid << 4;
    const int qb   = blockIdx.x;
    const int h    = blockIdx.y;
    const int b    = blockIdx.z;

    const int srow = tid >> 1;
    const int shf  = tid & 1;
    const int s    = srow & 7;
    const uint32_t sb = smem_u32(sm);

    // ---- stage Q (pre-scaled hi/lo from gmem) ----
    {
        size_t base = (size_t)(b * SEQ + qb * 64 + srow) * KQ + h * 32 + shf * 16;
#pragma unroll
        for (int i = 0; i < 4; i++) {
            uint4 vh4 = *(const uint4*)(g_qkvh + base + i * 4);
            uint4 vl4 = *(const uint4*)(g_qkvl + base + i * 4);
            int p0 = shf * 16 + i * 4;
            int sbase = ((p0 >> 3) * 64 + srow) * 8;
            int kp = p0 & 7;
            Qh[sbase + ((kp + 0) ^ s)] = vh4.x;
            Qh[sbase + ((kp + 1) ^ s)] = vh4.y;
            Qh[sbase + ((kp + 2) ^ s)] = vh4.z;
            Qh[sbase + ((kp + 3) ^ s)] = vh4.w;
            Ql[sbase + ((kp + 0) ^ s)] = vl4.x;
            Ql[sbase + ((kp + 1) ^ s)] = vl4.y;
            Ql[sbase + ((kp + 2) ^ s)] = vl4.z;
            Ql[sbase + ((kp + 3) ^ s)] = vl4.w;
        }
    }

    float m0 = -1e30f, m1 = -1e30f, l0s = 0.f, l1s = 0.f;
    float oacc[8][4];
#pragma unroll
    for (int j = 0; j < 8; j++)
#pragma unroll
        for (int q = 0; q < 4; q++) oacc[j][q] = 0.f;

    const int c0 = tg ^ g;
    const int c1 = (tg + 4) ^ g;

    for (int kb = 0; kb <= qb; kb++) {
        __syncthreads();

        // ---- V^T hi/lo via cp.async (linear layout, overlaps K staging) ----
        {
            size_t vbase = ((size_t)(b * NH + h) * HD + srow) * (SEQ / 2) + kb * 32 + shf * 16;
            const int d36 = srow * 36 + shf * 16;
            uint32_t vdstH = sb + (8192 + d36) * 4;
            uint32_t vdstL = sb + (10496 + d36) * 4;
#pragma unroll
            for (int i = 0; i < 4; i++) {
                cp16(vdstH + i * 16, g_vth + vbase + i * 4);
                cp16(vdstL + i * 16, g_vtl + vbase + i * 4);
            }
            CP_COMMIT();
        }

        // ---- stage K hi/lo (scalar scatter, swizzled) ----
        {
            size_t base = (size_t)(b * SEQ + kb * 64 + srow) * KQ + 512 + h * 32 + shf * 16;
#pragma unroll
            for (int i = 0; i < 4; i++) {
                uint4 vh4 = *(const uint4*)(g_qkvh + base + i * 4);
                uint4 vl4 = *(const uint4*)(g_qkvl + base + i * 4);
                int p0 = shf * 16 + i * 4;
                int sbase = ((p0 >> 3) * 64 + srow) * 8;
                int kp = p0 & 7;
                Kh[sbase + ((kp + 0) ^ s)] = vh4.x;
                Kh[sbase + ((kp + 1) ^ s)] = vh4.y;
                Kh[sbase + ((kp + 2) ^ s)] = vh4.z;
                Kh[sbase + ((kp + 3) ^ s)] = vh4.w;
                Kl[sbase + ((kp + 0) ^ s)] = vl4.x;
                Kl[sbase + ((kp + 1) ^ s)] = vl4.y;
                Kl[sbase + ((kp + 2) ^ s)] = vl4.z;
                Kl[sbase + ((kp + 3) ^ s)] = vl4.w;
            }
        }
        cp_wait<0>();
        __syncthreads();

        // ---- S = Q K^T, 3-term ----
        float sacc[8][4];
#pragma unroll
        for (int j = 0; j < 8; j++)
#pragma unroll
            for (int q = 0; q < 4; q++) sacc[j][q] = 0.f;

#pragma unroll
        for (int c = 0; c < 4; c++) {
            uint32_t a[4], bb[8][2];
            const int ab  = c * 512 + (rb + g) * 8;
            const int ab8 = c * 512 + (rb + g + 8) * 8;
            a[0] = Qh[ab + c0];  a[1] = Qh[ab8 + c0];
            a[2] = Qh[ab + c1];  a[3] = Qh[ab8 + c1];
#pragma unroll
            for (int j = 0; j < 8; j++) {
                int nb = c * 512 + (j * 8 + g) * 8;
                bb[j][0] = Kh[nb + c0];
                bb[j][1] = Kh[nb + c1];
            }
#pragma unroll
            for (int j = 0; j < 8; j++) mma_bf16(sacc[j], a, bb[j]);
#pragma unroll
            for (int j = 0; j < 8; j++) {
                int nb = c * 512 + (j * 8 + g) * 8;
                bb[j][0] = Kl[nb + c0];
                bb[j][1] = Kl[nb + c1];
            }
#pragma unroll
            for (int j = 0; j < 8; j++) mma_bf16(sacc[j], a, bb[j]);
            a[0] = Ql[ab + c0];  a[1] = Ql[ab8 + c0];
            a[2] = Ql[ab + c1];  a[3] = Ql[ab8 + c1];
#pragma unroll
            for (int j = 0; j < 8; j++) {
                int nb = c * 512 + (j * 8 + g) * 8;
                bb[j][0] = Kh[nb + c0];
                bb[j][1] = Kh[nb + c1];
            }
#pragma unroll
            for (int j = 0; j < 8; j++) mma_bf16(sacc[j], a, bb[j]);
        }

        // ---- causal mask on diagonal block ----
        if (kb == qb) {
            const int r0 = rb + g, r1 = rb + g + 8;
#pragma unroll
            for (int j = 0; j < 8; j++) {
                int col = j * 8 + 2 * tg;
                if (col     > r0) sacc[j][0] = -1e30f;
                if (col + 1 > r0) sacc[j][1] = -1e30f;
                if (col     > r1) sacc[j][2] = -1e30f;
                if (col + 1 > r1) sacc[j][3] = -1e30f;
            }
        }

        // ---- online softmax ----
        float mx0 = -1e30f, mx1 = -1e30f;
#pragma unroll
        for (int j = 0; j < 8; j++) {
            mx0 = fmaxf(mx0, fmaxf(sacc[j][0], sacc[j][1]));
            mx1 = fmaxf(mx1, fmaxf(sacc[j][2], sacc[j][3]));
        }
        mx0 = fmaxf(mx0, __shfl_xor_sync(0xffffffffu, mx0, 1));
        mx0 = fmaxf(mx0, __shfl_xor_sync(0xffffffffu, mx0, 2));
        mx1 = fmaxf(mx1, __shfl_xor_sync(0xffffffffu, mx1, 1));
        mx1 = fmaxf(mx1, __shfl_xor_sync(0xffffffffu, mx1, 2));

        float mn0 = fmaxf(m0, mx0), mn1 = fmaxf(m1, mx1);
        float al0 = __expf(m0 - mn0), al1 = __expf(m1 - mn1);
        m0 = mn0; m1 = mn1;

        float rs0 = 0.f, rs1 = 0.f;
#pragma unroll
        for (int j = 0; j < 8; j++) {
            sacc[j][0] = __expf(sacc[j][0] - mn0); rs0 += sacc[j][0];
            sacc[j][1] = __expf(sacc[j][1] - mn0); rs0 += sacc[j][1];
            sacc[j][2] = __expf(sacc[j][2] - mn1); rs1 += sacc[j][2];
            sacc[j][3] = __expf(sacc[j][3] - mn1); rs1 += sacc[j][3];
        }
        rs0 += __shfl_xor_sync(0xffffffffu, rs0, 1);
        rs0 += __shfl_xor_sync(0xffffffffu, rs0, 2);
        rs1 += __shfl_xor_sync(0xffffffffu, rs1, 1);
        rs1 += __shfl_xor_sync(0xffffffffu, rs1, 2);
        l0s = l0s * al0 + rs0;
        l1s = l1s * al1 + rs1;

#pragma unroll
        for (int j = 0; j < 8; j++) {
            oacc[j][0] *= al0; oacc[j][1] *= al0;
            oacc[j][2] *= al1; oacc[j][3] *= al1;
        }

        // ---- O += P V, 3-term ----
#pragma unroll
        for (int cc = 0; cc < 4; cc++) {
            uint32_t ph[4], pl[4];
            split2(sacc[2 * cc][0],     sacc[2 * cc][1],     ph[0], pl[0]);
            split2(sacc[2 * cc][2],     sacc[2 * cc][3],     ph[1], pl[1]);
            split2(sacc[2 * cc + 1][0], sacc[2 * cc + 1][1], ph[2], pl[2]);
            split2(sacc[2 * cc + 1][2], sacc[2 * cc + 1][3], ph[3], pl[3]);
#pragma unroll
            for (int j2 = 0; j2 < 8; j2++) {
                int vo = (j2 * 8 + g) * 36 + cc * 8 + tg;
                uint32_t vh2[2] = { Vh[vo], Vh[vo + 4] };
                uint32_t vl2[2] = { Vl[vo], Vl[vo + 4] };
                mma_bf16(oacc[j2], ph, vh2);
                mma_bf16(oacc[j2], pl, vh2);
                mma_bf16(oacc[j2], ph, vl2);
            }
        }
    }

    // ---- finalize: write hi/lo bf16x2 directly for GEMM2 ----
    const float inv0 = 1.0f / l0s, inv1 = 1.0f / l1s;
    const size_t row0 = (size_t)(b * SEQ + qb * 64 + rb + g);
#pragma unroll
    for (int j2 = 0; j2 < 8; j2++) {
        uint32_t h0, l0, h1, l1;
        split2(oacc[j2][0] * inv0, oacc[j2][1] * inv0, h0, l0);
        split2(oacc[j2][2] * inv1, oacc[j2][3] * inv1, h1, l1);
        size_t idx0 = row0 * KH + h * 32 + j2 * 4 + tg;
        g_ah[idx0]            = h0;
        g_al[idx0]            = l0;
        g_ah[idx0 + 8 * KH]   = h1;
        g_al[idx0 + 8 * KH]   = l1;
    }
}

// ---------------------------------------------------------------------------
// launch
// ---------------------------------------------------------------------------
extern "C" void kernel_launch(void* const* d_in, const int* in_sizes, int n_in,
                              void* d_out, int out_size) {
    const float* x    = (const float*)d_in[0];   // [4,2048,1024]
    const float* Wqkv = (const float*)d_in[1];   // [3072,1024]
    const float* Wout = (const float*)d_in[2];   // [1024,1024]
    float*       out  = (float*)d_out;           // [4,2048,1024]

    uint32_t *xh, *xl, *wqh, *wql, *woh, *wol, *ah, *al;
    cudaGetSymbolAddress((void**)&xh,  g_xh);
    cudaGetSymbolAddress((void**)&xl,  g_xl);
    cudaGetSymbolAddress((void**)&wqh, g_wqh);
    cudaGetSymbolAddress((void**)&wql, g_wql);
    cudaGetSymbolAddress((void**)&woh, g_woh);
    cudaGetSymbolAddress((void**)&wol, g_wol);
    cudaGetSymbolAddress((void**)&ah,  g_ah);
    cudaGetSymbolAddress((void**)&al,  g_al);

    cudaFuncSetAttribute(attn_mma, cudaFuncAttributeMaxDynamicSharedMemorySize, AT_SMEM);

    // 0) split inputs
    const int n2x = ROWS * KH;
    const int n2q = QKVD * KH;
    const int n2o = DIMX * KH;
    cvt_split<<<n2x / 256, 256>>>(x,    xh,  xl,  n2x);
    cvt_split<<<n2q / 256, 256>>>(Wqkv, wqh, wql, n2q);
    cvt_split<<<n2o / 256, 256>>>(Wout, woh, wol, n2o);

    // 1) qkv = x @ Wqkv^T — fused epilogue writes split hi/lo (+ fp32 V third)
    dim3 g1(QKVD / 128, ROWS / 128);
    gemm_bf3<1><<<g1, 256>>>(xh, xl, wqh, wql, nullptr, ROWS, QKVD, DIMX);

    // 1b) build transposed V hi/lo
    dim3 gv(SEQ / 32, BATCH * NH);
    cvt_vT<<<gv, 256>>>();

    // 2) causal attention -> g_ah/g_al (bf16x2 hi/lo)
    dim3 g2(SEQ / 64, NH, BATCH);
    attn_mma<<<g2, 128, AT_SMEM>>>();

    // 3) out = att @ Wout^T [8192,1024]
    dim3 g3(DIMX / 128, ROWS / 128);
    gemm_bf3<0><<<g3, 256>>>(ah, al, woh, wol, out, ROWS, DIMX, DIMX);
}